// round 9
// baseline (speedup 1.0000x reference)
#include <cuda_runtime.h>
#include <cuda_fp16.h>
#include <math_constants.h>
#include <cstdint>

// Problem constants (registry shapes)
#define MAX_NODES 100000
#define HIDDEN 128
#define MAX_EDGES 1000000

#define EXP_BLOCKS 1024
#define SCALE_BLOCKS 1184

// Scratch (allocation-free rule: __device__ globals)
__device__ __half g_A[MAX_NODES * HIDDEN];      // emb @ W1[:128] + b1 (folded)
__device__ __half g_B[MAX_NODES * HIDDEN];      // emb @ W1[128:]
__device__ __half g_emb16[MAX_NODES * HIDDEN];  // fp16 copy of emb
__device__ __half g_Wt[256 * 128];              // Wt[n][k] = Wcat[k][n], fp16
__device__ float g_logits[MAX_EDGES];
__device__ unsigned g_pmax2[256];               // bucketed max (orderable-uint keys)
__device__ float g_psum[EXP_BLOCKS];

__device__ __forceinline__ uint32_t smem_u32(const void* p) {
    uint32_t a;
    asm("{ .reg .u64 t; cvta.to.shared.u64 t, %1; cvt.u32.u64 %0, t; }"
        : "=r"(a) : "l"(p));
    return a;
}

// float <-> monotone-orderable uint (max is order-independent => atomics OK)
__device__ __forceinline__ unsigned fenc(float f) {
    unsigned u = __float_as_uint(f);
    return (u & 0x80000000u) ? ~u : (u | 0x80000000u);
}
__device__ __forceinline__ float fdec(unsigned u) {
    unsigned b = (u & 0x80000000u) ? (u & 0x7FFFFFFFu) : ~u;
    return __uint_as_float(b);
}

#define LDSM_X4(r0, r1, r2, r3, addr) asm volatile( \
    "ldmatrix.sync.aligned.m8n8.x4.shared.b16 {%0,%1,%2,%3}, [%4];" \
    : "=r"(r0), "=r"(r1), "=r"(r2), "=r"(r3) : "r"(addr))

#define MMA16816(c, a, b) asm volatile( \
    "mma.sync.aligned.m16n8k16.row.col.f32.f16.f16.f32 " \
    "{%0,%1,%2,%3}, {%4,%5,%6,%7}, {%8,%9}, {%0,%1,%2,%3};" \
    : "+f"((c)[0]), "+f"((c)[1]), "+f"((c)[2]), "+f"((c)[3]) \
    : "r"((a)[0]), "r"((a)[1]), "r"((a)[2]), "r"((a)[3]), \
      "r"((b)[0]), "r"((b)[1]))

#define CP_ASYNC16(dst, src) asm volatile( \
    "cp.async.cg.shared.global [%0], [%1], 16;" :: "r"(dst), "l"(src))
#define CP_ASYNC16Z(dst, src, sz) asm volatile( \
    "cp.async.cg.shared.global [%0], [%1], 16, %2;" :: "r"(dst), "l"(src), "r"(sz))
#define CP_COMMIT() asm volatile("cp.async.commit_group;" ::: "memory")
#define CP_WAIT(n) asm volatile("cp.async.wait_group %0;" :: "n"(n) : "memory")

// ---------------------------------------------------------------------------
// Prep A: emb fp32 -> fp16 (unit = 8 elements per thread, uint4 stores)
// ---------------------------------------------------------------------------
__global__ void emb16_kernel(const float* __restrict__ emb, int n8)
{
    int i = blockIdx.x * 256 + threadIdx.x;
    if (i >= n8) return;
    const float4* src = (const float4*)emb + (size_t)i * 2;
    float4 v0 = src[0], v1 = src[1];
    __half2 h0 = __floats2half2_rn(v0.x, v0.y);
    __half2 h1 = __floats2half2_rn(v0.z, v0.w);
    __half2 h2 = __floats2half2_rn(v1.x, v1.y);
    __half2 h3 = __floats2half2_rn(v1.z, v1.w);
    uint4 o = make_uint4(*(uint32_t*)&h0, *(uint32_t*)&h1,
                         *(uint32_t*)&h2, *(uint32_t*)&h3);
    *((uint4*)g_emb16 + i) = o;
}

// ---------------------------------------------------------------------------
// Prep B: Wt[n][k] = W1[k][n] (n<128) | W1[128+k][n-128] (n>=128), as fp16.
// Also initializes the 256 max buckets.
// ---------------------------------------------------------------------------
__global__ void wt_kernel(const float* __restrict__ W1)
{
    int n = blockIdx.x;           // 0..255
    int k = threadIdx.x;          // 0..127
    if (k == 0) g_pmax2[n] = 0u;
    float v = (n < HIDDEN) ? W1[k * HIDDEN + n]
                           : W1[(HIDDEN + k) * HIDDEN + (n - HIDDEN)];
    g_Wt[n * HIDDEN + k] = __float2half_rn(v);
}

// ---------------------------------------------------------------------------
// Phase 1: HMMA GEMM. grid = (ceil(tiles/2), 2). Each CTA: two 128-row
// m-tiles (double-buffered cp.async from g_emb16) x one 128-col N half.
// B loaded once per CTA. Epilogue staged through SMEM for coalesced STG.128.
// ---------------------------------------------------------------------------
#define SMA_STRIDE 136
#define ABUF_BYTES (128 * SMA_STRIDE * 2)              // 34816
#define SB_OFF (2 * ABUF_BYTES)                        // 69632
#define SM_TOTAL (SB_OFF + ABUF_BYTES)                 // 104448

__global__ __launch_bounds__(256, 2)
void gemm_mma_kernel(const float* __restrict__ b1, int M, int num_tiles)
{
    extern __shared__ char smem[];
    const int tid = threadIdx.x;
    const int lane = tid & 31;
    const int wid = tid >> 5;
    const int nb = blockIdx.y;
    const int t0 = blockIdx.x * 2;
    const bool has2 = (t0 + 1 < num_tiles);
    const uint32_t sbase = smem_u32(smem);

    // Group 0: A tile 0 + B half-tile (2048 16B chunks each, 8/thread)
    {
        const int m0 = t0 * 128;
#pragma unroll
        for (int i = 0; i < 8; i++) {
            int idx = tid + i * 256;
            int row = idx >> 4, q = idx & 15;
            uint32_t dst = sbase + (uint32_t)((row * SMA_STRIDE + q * 8) * 2);
            int gr = m0 + row;
            const __half* src = g_emb16 + (size_t)(gr < M ? gr : 0) * HIDDEN + q * 8;
            CP_ASYNC16Z(dst, src, (gr < M) ? 16u : 0u);
        }
        const __half* WtB = g_Wt + (size_t)nb * 128 * HIDDEN;
#pragma unroll
        for (int i = 0; i < 8; i++) {
            int idx = tid + i * 256;
            int row = idx >> 4, q = idx & 15;
            uint32_t dst = sbase + SB_OFF + (uint32_t)((row * SMA_STRIDE + q * 8) * 2);
            CP_ASYNC16(dst, WtB + row * HIDDEN + q * 8);
        }
        CP_COMMIT();
    }
    // Group 1: A tile 1 (overlaps with tile-0 compute)
    if (has2) {
        const int m0 = (t0 + 1) * 128;
#pragma unroll
        for (int i = 0; i < 8; i++) {
            int idx = tid + i * 256;
            int row = idx >> 4, q = idx & 15;
            uint32_t dst = sbase + ABUF_BYTES
                         + (uint32_t)((row * SMA_STRIDE + q * 8) * 2);
            int gr = m0 + row;
            const __half* src = g_emb16 + (size_t)(gr < M ? gr : 0) * HIDDEN + q * 8;
            CP_ASYNC16Z(dst, src, (gr < M) ? 16u : 0u);
        }
    }
    CP_COMMIT();
    CP_WAIT(1);                 // group 0 (A0 + B) complete
    __syncthreads();

    const int m_base = (wid >> 1) * 32;
    const int n_base = (wid & 1) * 64;
    const uint32_t sb = sbase + SB_OFF;
    const int arow = (lane & 7) + ((lane >> 3) & 1) * 8;
    const int akh  = ((lane >> 4) & 1) * 8;
    const int brow = lane & 7;
    const int bsel = lane >> 3;
    const int bnj  = (bsel >> 1) * 8;
    const int bkh  = (bsel & 1) * 8;
    const int ncol = (lane & 3) * 2;
    const int mrow = lane >> 2;
    __half* dst_tbl = (nb == 0) ? g_A : g_B;

    const int nt = has2 ? 2 : 1;
    for (int t = 0; t < nt; t++) {
        const uint32_t sa = sbase + (uint32_t)t * ABUF_BYTES;
        __half* SA = (__half*)(smem + t * ABUF_BYTES);
        const int m0 = (t0 + t) * 128;

        float c[2][8][4];
#pragma unroll
        for (int mi = 0; mi < 2; mi++)
#pragma unroll
            for (int nj = 0; nj < 8; nj++)
#pragma unroll
                for (int q = 0; q < 4; q++) c[mi][nj][q] = 0.0f;

#pragma unroll
        for (int ks = 0; ks < 8; ks++) {
            const int k0 = ks * 16;
            uint32_t a[2][4];
#pragma unroll
            for (int mi = 0; mi < 2; mi++) {
                uint32_t addr = sa + (uint32_t)(((m_base + mi * 16 + arow) * SMA_STRIDE
                                                 + k0 + akh) * 2);
                LDSM_X4(a[mi][0], a[mi][1], a[mi][2], a[mi][3], addr);
            }
            uint32_t b[8][2];
#pragma unroll
            for (int p = 0; p < 4; p++) {
                uint32_t addr = sb + (uint32_t)(((n_base + p * 16 + bnj + brow) * SMA_STRIDE
                                                 + k0 + bkh) * 2);
                uint32_t r0, r1, r2, r3;
                LDSM_X4(r0, r1, r2, r3, addr);
                b[p * 2][0] = r0; b[p * 2][1] = r1;
                b[p * 2 + 1][0] = r2; b[p * 2 + 1][1] = r3;
            }
#pragma unroll
            for (int mi = 0; mi < 2; mi++)
#pragma unroll
                for (int nj = 0; nj < 8; nj++)
                    MMA16816(c[mi][nj], a[mi], b[nj]);
        }

        // Epilogue stage 1: frags -> SA[t] (all ldmatrix reads done first)
        __syncthreads();
#pragma unroll
        for (int mi = 0; mi < 2; mi++) {
            const int r0 = m_base + mi * 16 + mrow;
#pragma unroll
            for (int nj = 0; nj < 8; nj++) {
                int n = n_base + nj * 8 + ncol;
                float v0 = c[mi][nj][0], v1 = c[mi][nj][1];
                float v2 = c[mi][nj][2], v3 = c[mi][nj][3];
                if (nb == 0) {
                    float bb0 = __ldg(b1 + n), bb1 = __ldg(b1 + n + 1);
                    v0 += bb0; v1 += bb1; v2 += bb0; v3 += bb1;
                }
                *(__half2*)(SA + r0 * SMA_STRIDE + n)       = __floats2half2_rn(v0, v1);
                *(__half2*)(SA + (r0 + 8) * SMA_STRIDE + n) = __floats2half2_rn(v2, v3);
            }
        }
        __syncthreads();

        // Epilogue stage 2: coalesced STG.128
#pragma unroll
        for (int i = 0; i < 8; i++) {
            int idx = tid + i * 256;
            int row = idx >> 4;
            int q   = (idx & 15) * 8;
            if (m0 + row < M) {
                uint4 v = *(uint4*)(SA + row * SMA_STRIDE + q);
                *(uint4*)(dst_tbl + (size_t)(m0 + row) * HIDDEN + q) = v;
            }
        }

        if (t == 0 && has2) {
            CP_WAIT(0);          // A1 landed
            __syncthreads();
        }
    }
}

// ---------------------------------------------------------------------------
// Phase 2: per-edge logit. 8 lanes per edge, 4 edges per warp (MLP=8/warp).
// ---------------------------------------------------------------------------
__global__ __launch_bounds__(256) void edge_kernel(
    const int* __restrict__ srcs, const int* __restrict__ dsts,
    const float* __restrict__ W2, const float* __restrict__ b2,
    int E, int M)
{
    const int lane = threadIdx.x & 31;
    const int warp = threadIdx.x >> 5;    // 0..7
    const int grp  = lane >> 3;           // 0..3 edge within warp
    const int sub  = lane & 7;            // 0..7 feature slice
    const int e = (blockIdx.x * 8 + warp) * 4 + grp;

    float w[16];
    {
        const float4* w2p = (const float4*)(W2 + sub * 16);
#pragma unroll
        for (int q = 0; q < 4; q++) {
            float4 v = w2p[q];
            w[q * 4 + 0] = v.x; w[q * 4 + 1] = v.y;
            w[q * 4 + 2] = v.z; w[q * 4 + 3] = v.w;
        }
    }
    const float b2v = __ldg(b2);

    const bool has = (e < E);
    float p = 0.0f;
    if (has) {
        int s = srcs[e];
        int t = dsts[e];
        if ((unsigned)s >= (unsigned)M) s = 0;
        if ((unsigned)t >= (unsigned)M) t = 0;
        const __half* Ar = g_A + (size_t)s * HIDDEN + sub * 16;
        const __half* Br = g_B + (size_t)t * HIDDEN + sub * 16;
        uint4 a0  = *(const uint4*)(Ar);
        uint4 a1  = *(const uint4*)(Ar + 8);
        uint4 b0  = *(const uint4*)(Br);
        uint4 b1r = *(const uint4*)(Br + 8);

        const uint32_t* au  = (const uint32_t*)&a0;
        const uint32_t* bu  = (const uint32_t*)&b0;
#pragma unroll
        for (int i = 0; i < 4; i++) {
            float2 af = __half22float2(*(__half2*)&au[i]);
            float2 bf = __half22float2(*(__half2*)&bu[i]);
            float h0 = fmaxf(af.x + bf.x, 0.0f);
            float h1 = fmaxf(af.y + bf.y, 0.0f);
            p = fmaf(h0, w[2 * i], p);
            p = fmaf(h1, w[2 * i + 1], p);
        }
        const uint32_t* au2 = (const uint32_t*)&a1;
        const uint32_t* bu2 = (const uint32_t*)&b1r;
#pragma unroll
        for (int i = 0; i < 4; i++) {
            float2 af = __half22float2(*(__half2*)&au2[i]);
            float2 bf = __half22float2(*(__half2*)&bu2[i]);
            float h0 = fmaxf(af.x + bf.x, 0.0f);
            float h1 = fmaxf(af.y + bf.y, 0.0f);
            p = fmaf(h0, w[8 + 2 * i], p);
            p = fmaf(h1, w[8 + 2 * i + 1], p);
        }
    }
    p += __shfl_xor_sync(0xffffffffu, p, 4);
    p += __shfl_xor_sync(0xffffffffu, p, 2);
    p += __shfl_xor_sync(0xffffffffu, p, 1);
    const float logit = p + b2v;
    if (has && sub == 0) g_logits[e] = logit;

    float m = has ? logit : -CUDART_INF_F;
    m = fmaxf(m, __shfl_xor_sync(0xffffffffu, m, 8));
    m = fmaxf(m, __shfl_xor_sync(0xffffffffu, m, 16));
    if (lane == 0) atomicMax(&g_pmax2[blockIdx.x & 255], fenc(m));
}

// ---------------------------------------------------------------------------
// Phase 3: softmax. exp folds the 256-bucket max; scale folds the psum.
// ---------------------------------------------------------------------------
__global__ __launch_bounds__(256) void exp_kernel(float* __restrict__ out, int E)
{
    __shared__ float s[256];
    s[threadIdx.x] = fdec(g_pmax2[threadIdx.x]);
    __syncthreads();
#pragma unroll
    for (int o = 128; o > 0; o >>= 1) {
        if (threadIdx.x < o) s[threadIdx.x] = fmaxf(s[threadIdx.x], s[threadIdx.x + o]);
        __syncthreads();
    }
    const float m = s[0];
    __syncthreads();

    float acc = 0.0f;
    for (int i4 = (blockIdx.x * 256 + threadIdx.x) * 4; i4 < E; i4 += EXP_BLOCKS * 1024) {
        if (i4 + 3 < E) {
            float4 lg = *(const float4*)(g_logits + i4);
            float p0 = expf(lg.x - m), p1 = expf(lg.y - m);
            float p2 = expf(lg.z - m), p3 = expf(lg.w - m);
            *(float4*)(out + i4) = make_float4(p0, p1, p2, p3);
            acc += (p0 + p1) + (p2 + p3);
        } else {
            for (int i = i4; i < E; i++) {
                float p = expf(g_logits[i] - m);
                out[i] = p;
                acc += p;
            }
        }
    }
    s[threadIdx.x] = acc;
    __syncthreads();
#pragma unroll
    for (int o = 128; o > 0; o >>= 1) {
        if (threadIdx.x < o) s[threadIdx.x] += s[threadIdx.x + o];
        __syncthreads();
    }
    if (threadIdx.x == 0) g_psum[blockIdx.x] = s[0];
}

__global__ __launch_bounds__(256) void scale_kernel(float* __restrict__ out, int E)
{
    __shared__ float s[256];
    float a = 0.0f;
#pragma unroll
    for (int i = 0; i < EXP_BLOCKS / 256; i++)
        a += g_psum[threadIdx.x + i * 256];
    s[threadIdx.x] = a;
    __syncthreads();
#pragma unroll
    for (int o = 128; o > 0; o >>= 1) {
        if (threadIdx.x < o) s[threadIdx.x] += s[threadIdx.x + o];
        __syncthreads();
    }
    const float inv = 1.0f / s[0];

    const int stride = SCALE_BLOCKS * 1024;
    for (int i4 = (blockIdx.x * 256 + threadIdx.x) * 4; i4 < E; i4 += stride) {
        if (i4 + 3 < E) {
            float4 v = *(const float4*)(out + i4);
            v.x *= inv; v.y *= inv; v.z *= inv; v.w *= inv;
            *(float4*)(out + i4) = v;
        } else {
            for (int i = i4; i < E; i++) out[i] *= inv;
        }
    }
}

// ---------------------------------------------------------------------------
extern "C" void kernel_launch(void* const* d_in, const int* in_sizes, int n_in,
                              void* d_out, int out_size)
{
    const float* emb = (const float*)d_in[0];
    const int*   lm  = (const int*)d_in[1];   // int32 (JAX x64-disabled)
    const float* W1  = (const float*)d_in[2];
    const float* b1  = (const float*)d_in[3];
    const float* W2  = (const float*)d_in[4];
    const float* b2  = (const float*)d_in[5];
    float* out = (float*)d_out;

    const int M = in_sizes[0] / HIDDEN;       // number of nodes
    const int E = in_sizes[1] / 2;            // number of edges
    const int* srcs = lm;
    const int* dsts = lm + E;

    cudaFuncSetAttribute(gemm_mma_kernel,
                         cudaFuncAttributeMaxDynamicSharedMemorySize, SM_TOTAL);

    const int num_tiles = (M + 127) / 128;
    const int edge_blocks = (E + 31) / 32;    // 32 edges per block
    dim3 gemm_grid((num_tiles + 1) / 2, 2);

    emb16_kernel<<<(M * 16 + 255) / 256, 256>>>(emb, M * 16);
    wt_kernel<<<256, 128>>>(W1);
    gemm_mma_kernel<<<gemm_grid, 256, SM_TOTAL>>>(b1, M, num_tiles);
    edge_kernel<<<edge_blocks, 256>>>(srcs, dsts, W2, b2, E, M);
    exp_kernel<<<EXP_BLOCKS, 256>>>(out, E);
    scale_kernel<<<SCALE_BLOCKS, 256>>>(out, E);
}

// round 10
// speedup vs baseline: 1.0411x; 1.0411x over previous
#include <cuda_runtime.h>
#include <cuda_fp16.h>
#include <math_constants.h>
#include <cstdint>

// Problem constants (registry shapes)
#define MAX_NODES 100000
#define HIDDEN 128
#define MAX_EDGES 1000000

#define EXP_BLOCKS 1024
#define SCALE_BLOCKS 1184

// Scratch (allocation-free rule: __device__ globals)
__device__ __half g_A[MAX_NODES * HIDDEN];      // emb @ W1[:128] + b1 (folded)
__device__ __half g_B[MAX_NODES * HIDDEN];      // emb @ W1[128:]
__device__ __half g_Wt[256 * 128];              // Wt[n][k] = Wcat[k][n], fp16
__device__ float g_logits[MAX_EDGES];
__device__ unsigned g_pmax2[256];               // bucketed max (orderable-uint keys)
__device__ float g_psum[EXP_BLOCKS];

__device__ __forceinline__ uint32_t smem_u32(const void* p) {
    uint32_t a;
    asm("{ .reg .u64 t; cvta.to.shared.u64 t, %1; cvt.u32.u64 %0, t; }"
        : "=r"(a) : "l"(p));
    return a;
}

// float <-> monotone-orderable uint (max is order-independent => atomics OK)
__device__ __forceinline__ unsigned fenc(float f) {
    unsigned u = __float_as_uint(f);
    return (u & 0x80000000u) ? ~u : (u | 0x80000000u);
}
__device__ __forceinline__ float fdec(unsigned u) {
    unsigned b = (u & 0x80000000u) ? (u & 0x7FFFFFFFu) : ~u;
    return __uint_as_float(b);
}

#define LDSM_X4(r0, r1, r2, r3, addr) asm volatile( \
    "ldmatrix.sync.aligned.m8n8.x4.shared.b16 {%0,%1,%2,%3}, [%4];" \
    : "=r"(r0), "=r"(r1), "=r"(r2), "=r"(r3) : "r"(addr))

#define MMA16816(c, a, b) asm volatile( \
    "mma.sync.aligned.m16n8k16.row.col.f32.f16.f16.f32 " \
    "{%0,%1,%2,%3}, {%4,%5,%6,%7}, {%8,%9}, {%0,%1,%2,%3};" \
    : "+f"((c)[0]), "+f"((c)[1]), "+f"((c)[2]), "+f"((c)[3]) \
    : "r"((a)[0]), "r"((a)[1]), "r"((a)[2]), "r"((a)[3]), \
      "r"((b)[0]), "r"((b)[1]))

// ---------------------------------------------------------------------------
// Prep: Wt[n][k] = W1[k][n] (n<128) | W1[128+k][n-128] (n>=128), as fp16.
// Also initializes the 256 max buckets.
// ---------------------------------------------------------------------------
__global__ void wt_kernel(const float* __restrict__ W1)
{
    int n = blockIdx.x;           // 0..255
    int k = threadIdx.x;          // 0..127
    if (k == 0) g_pmax2[n] = 0u;
    float v = (n < HIDDEN) ? W1[k * HIDDEN + n]
                           : W1[(HIDDEN + k) * HIDDEN + (n - HIDDEN)];
    g_Wt[n * HIDDEN + k] = __float2half_rn(v);
}

// ---------------------------------------------------------------------------
// Phase 1: HMMA GEMM (R8 form — fastest measured). N-split grid.y:
// 0 -> g_A half (+b1), 1 -> g_B half. Per CTA: D[128,128]. 256 threads,
// warp tile 32x64. Epilogue staged through SMEM for coalesced STG.128.
// ---------------------------------------------------------------------------
#define SMA_STRIDE 136
#define SB_OFF (128 * SMA_STRIDE * 2)                  // 34816
#define SM_TOTAL (SB_OFF + 128 * SMA_STRIDE * 2)       // 69632

__global__ __launch_bounds__(256, 2)
void gemm_mma_kernel(const float* __restrict__ emb, const float* __restrict__ b1, int M)
{
    extern __shared__ char smem[];
    __half* SA = (__half*)smem;
    __half* SB = (__half*)(smem + SB_OFF);
    const int tid = threadIdx.x;
    const int lane = tid & 31;
    const int wid = tid >> 5;
    const int m0 = blockIdx.x * 128;
    const int nb = blockIdx.y;

    // Load A tile: 128 rows x 128 k, fp32 -> fp16. 4096 float4, 16/thread.
#pragma unroll
    for (int i = 0; i < 16; i++) {
        int idx = tid + i * 256;
        int row = idx >> 5;
        int k4  = (idx & 31) * 4;
        float4 v = make_float4(0.f, 0.f, 0.f, 0.f);
        if (m0 + row < M) v = *(const float4*)(emb + (size_t)(m0 + row) * HIDDEN + k4);
        __half2 h01 = __floats2half2_rn(v.x, v.y);
        __half2 h23 = __floats2half2_rn(v.z, v.w);
        uint2 pack = make_uint2(*(uint32_t*)&h01, *(uint32_t*)&h23);
        *(uint2*)(SA + row * SMA_STRIDE + k4) = pack;
    }
    // Load B half-tile: 128 n x 128 k fp16 from g_Wt.
    const __half* WtB = g_Wt + (size_t)nb * 128 * HIDDEN;
#pragma unroll
    for (int i = 0; i < 16; i++) {
        int idx = tid + i * 256;
        int n   = idx >> 5;
        int k4  = (idx & 31) * 4;
        uint2 v = *(const uint2*)(WtB + n * HIDDEN + k4);
        *(uint2*)(SB + n * SMA_STRIDE + k4) = v;
    }
    __syncthreads();

    const int m_base = (wid >> 1) * 32;
    const int n_base = (wid & 1) * 64;
    const uint32_t sa = smem_u32(SA);
    const uint32_t sb = smem_u32(SB);

    float c[2][8][4];
#pragma unroll
    for (int mi = 0; mi < 2; mi++)
#pragma unroll
        for (int nj = 0; nj < 8; nj++)
#pragma unroll
            for (int q = 0; q < 4; q++) c[mi][nj][q] = 0.0f;

    const int arow = (lane & 7) + ((lane >> 3) & 1) * 8;
    const int akh  = ((lane >> 4) & 1) * 8;
    const int brow = lane & 7;
    const int bsel = lane >> 3;
    const int bnj  = (bsel >> 1) * 8;
    const int bkh  = (bsel & 1) * 8;

#pragma unroll
    for (int ks = 0; ks < 8; ks++) {
        const int k0 = ks * 16;
        uint32_t a[2][4];
#pragma unroll
        for (int mi = 0; mi < 2; mi++) {
            uint32_t addr = sa + (uint32_t)(((m_base + mi * 16 + arow) * SMA_STRIDE
                                             + k0 + akh) * 2);
            LDSM_X4(a[mi][0], a[mi][1], a[mi][2], a[mi][3], addr);
        }
        uint32_t b[8][2];
#pragma unroll
        for (int p = 0; p < 4; p++) {
            uint32_t addr = sb + (uint32_t)(((n_base + p * 16 + bnj + brow) * SMA_STRIDE
                                             + k0 + bkh) * 2);
            uint32_t r0, r1, r2, r3;
            LDSM_X4(r0, r1, r2, r3, addr);
            b[p * 2][0] = r0; b[p * 2][1] = r1;
            b[p * 2 + 1][0] = r2; b[p * 2 + 1][1] = r3;
        }
#pragma unroll
        for (int mi = 0; mi < 2; mi++)
#pragma unroll
            for (int nj = 0; nj < 8; nj++)
                MMA16816(c[mi][nj], a[mi], b[nj]);
    }

    // Epilogue stage 1: frags -> SA (stride 136 keeps STS conflict-free).
    __syncthreads();
    const int ncol = (lane & 3) * 2;
    const int mrow = lane >> 2;
#pragma unroll
    for (int mi = 0; mi < 2; mi++) {
        const int r0 = m_base + mi * 16 + mrow;
#pragma unroll
        for (int nj = 0; nj < 8; nj++) {
            int n = n_base + nj * 8 + ncol;
            float v0 = c[mi][nj][0], v1 = c[mi][nj][1];
            float v2 = c[mi][nj][2], v3 = c[mi][nj][3];
            if (nb == 0) {
                float bb0 = __ldg(b1 + n), bb1 = __ldg(b1 + n + 1);
                v0 += bb0; v1 += bb1; v2 += bb0; v3 += bb1;
            }
            *(__half2*)(SA + r0 * SMA_STRIDE + n)       = __floats2half2_rn(v0, v1);
            *(__half2*)(SA + (r0 + 8) * SMA_STRIDE + n) = __floats2half2_rn(v2, v3);
        }
    }
    __syncthreads();

    // Epilogue stage 2: coalesced STG.128. 2048 uint4, 8/thread.
    __half* dst_tbl = (nb == 0) ? g_A : g_B;
#pragma unroll
    for (int i = 0; i < 8; i++) {
        int idx = tid + i * 256;          // 0..2047
        int row = idx >> 4;               // 0..127
        int q   = (idx & 15) * 8;         // half offset within row
        if (m0 + row < M) {
            uint4 v = *(uint4*)(SA + row * SMA_STRIDE + q);
            *(uint4*)(dst_tbl + (size_t)(m0 + row) * HIDDEN + q) = v;
        }
    }
}

// ---------------------------------------------------------------------------
// Phase 2: per-edge logit. 8 lanes per edge, 4 edges per warp (MLP=8/warp).
// Gathers use __ldcg (L2-only): tables are L2-resident with zero reuse per
// line at L1, so L1 line-fill/allocation is pure overhead (ncu: L1 90.6%).
// ---------------------------------------------------------------------------
__global__ __launch_bounds__(256) void edge_kernel(
    const int* __restrict__ srcs, const int* __restrict__ dsts,
    const float* __restrict__ W2, const float* __restrict__ b2,
    int E, int M)
{
    const int lane = threadIdx.x & 31;
    const int warp = threadIdx.x >> 5;    // 0..7
    const int grp  = lane >> 3;           // 0..3 edge within warp
    const int sub  = lane & 7;            // 0..7 feature slice
    const int e = (blockIdx.x * 8 + warp) * 4 + grp;

    float w[16];
    {
        const float4* w2p = (const float4*)(W2 + sub * 16);
#pragma unroll
        for (int q = 0; q < 4; q++) {
            float4 v = w2p[q];
            w[q * 4 + 0] = v.x; w[q * 4 + 1] = v.y;
            w[q * 4 + 2] = v.z; w[q * 4 + 3] = v.w;
        }
    }
    const float b2v = __ldg(b2);

    const bool has = (e < E);
    float p = 0.0f;
    if (has) {
        int s = srcs[e];
        int t = dsts[e];
        if ((unsigned)s >= (unsigned)M) s = 0;
        if ((unsigned)t >= (unsigned)M) t = 0;
        const __half* Ar = g_A + (size_t)s * HIDDEN + sub * 16;
        const __half* Br = g_B + (size_t)t * HIDDEN + sub * 16;
        uint4 a0  = __ldcg((const uint4*)(Ar));
        uint4 a1  = __ldcg((const uint4*)(Ar + 8));
        uint4 b0  = __ldcg((const uint4*)(Br));
        uint4 b1r = __ldcg((const uint4*)(Br + 8));

        const uint32_t* au  = (const uint32_t*)&a0;
        const uint32_t* bu  = (const uint32_t*)&b0;
#pragma unroll
        for (int i = 0; i < 4; i++) {
            float2 af = __half22float2(*(__half2*)&au[i]);
            float2 bf = __half22float2(*(__half2*)&bu[i]);
            float h0 = fmaxf(af.x + bf.x, 0.0f);
            float h1 = fmaxf(af.y + bf.y, 0.0f);
            p = fmaf(h0, w[2 * i], p);
            p = fmaf(h1, w[2 * i + 1], p);
        }
        const uint32_t* au2 = (const uint32_t*)&a1;
        const uint32_t* bu2 = (const uint32_t*)&b1r;
#pragma unroll
        for (int i = 0; i < 4; i++) {
            float2 af = __half22float2(*(__half2*)&au2[i]);
            float2 bf = __half22float2(*(__half2*)&bu2[i]);
            float h0 = fmaxf(af.x + bf.x, 0.0f);
            float h1 = fmaxf(af.y + bf.y, 0.0f);
            p = fmaf(h0, w[8 + 2 * i], p);
            p = fmaf(h1, w[8 + 2 * i + 1], p);
        }
    }
    p += __shfl_xor_sync(0xffffffffu, p, 4);
    p += __shfl_xor_sync(0xffffffffu, p, 2);
    p += __shfl_xor_sync(0xffffffffu, p, 1);
    const float logit = p + b2v;
    if (has && sub == 0) g_logits[e] = logit;

    float m = has ? logit : -CUDART_INF_F;
    m = fmaxf(m, __shfl_xor_sync(0xffffffffu, m, 8));
    m = fmaxf(m, __shfl_xor_sync(0xffffffffu, m, 16));
    if (lane == 0) atomicMax(&g_pmax2[blockIdx.x & 255], fenc(m));
}

// ---------------------------------------------------------------------------
// Phase 3: softmax. exp folds the 256-bucket max; scale folds the psum.
// ---------------------------------------------------------------------------
__global__ __launch_bounds__(256) void exp_kernel(float* __restrict__ out, int E)
{
    __shared__ float s[256];
    s[threadIdx.x] = fdec(g_pmax2[threadIdx.x]);
    __syncthreads();
#pragma unroll
    for (int o = 128; o > 0; o >>= 1) {
        if (threadIdx.x < o) s[threadIdx.x] = fmaxf(s[threadIdx.x], s[threadIdx.x + o]);
        __syncthreads();
    }
    const float m = s[0];
    __syncthreads();

    float acc = 0.0f;
    for (int i4 = (blockIdx.x * 256 + threadIdx.x) * 4; i4 < E; i4 += EXP_BLOCKS * 1024) {
        if (i4 + 3 < E) {
            float4 lg = *(const float4*)(g_logits + i4);
            float p0 = expf(lg.x - m), p1 = expf(lg.y - m);
            float p2 = expf(lg.z - m), p3 = expf(lg.w - m);
            *(float4*)(out + i4) = make_float4(p0, p1, p2, p3);
            acc += (p0 + p1) + (p2 + p3);
        } else {
            for (int i = i4; i < E; i++) {
                float p = expf(g_logits[i] - m);
                out[i] = p;
                acc += p;
            }
        }
    }
    s[threadIdx.x] = acc;
    __syncthreads();
#pragma unroll
    for (int o = 128; o > 0; o >>= 1) {
        if (threadIdx.x < o) s[threadIdx.x] += s[threadIdx.x + o];
        __syncthreads();
    }
    if (threadIdx.x == 0) g_psum[blockIdx.x] = s[0];
}

__global__ __launch_bounds__(256) void scale_kernel(float* __restrict__ out, int E)
{
    __shared__ float s[256];
    float a = 0.0f;
#pragma unroll
    for (int i = 0; i < EXP_BLOCKS / 256; i++)
        a += g_psum[threadIdx.x + i * 256];
    s[threadIdx.x] = a;
    __syncthreads();
#pragma unroll
    for (int o = 128; o > 0; o >>= 1) {
        if (threadIdx.x < o) s[threadIdx.x] += s[threadIdx.x + o];
        __syncthreads();
    }
    const float inv = 1.0f / s[0];

    const int stride = SCALE_BLOCKS * 1024;
    for (int i4 = (blockIdx.x * 256 + threadIdx.x) * 4; i4 < E; i4 += stride) {
        if (i4 + 3 < E) {
            float4 v = *(const float4*)(out + i4);
            v.x *= inv; v.y *= inv; v.z *= inv; v.w *= inv;
            *(float4*)(out + i4) = v;
        } else {
            for (int i = i4; i < E; i++) out[i] *= inv;
        }
    }
}

// ---------------------------------------------------------------------------
extern "C" void kernel_launch(void* const* d_in, const int* in_sizes, int n_in,
                              void* d_out, int out_size)
{
    const float* emb = (const float*)d_in[0];
    const int*   lm  = (const int*)d_in[1];   // int32 (JAX x64-disabled)
    const float* W1  = (const float*)d_in[2];
    const float* b1  = (const float*)d_in[3];
    const float* W2  = (const float*)d_in[4];
    const float* b2  = (const float*)d_in[5];
    float* out = (float*)d_out;

    const int M = in_sizes[0] / HIDDEN;       // number of nodes
    const int E = in_sizes[1] / 2;            // number of edges
    const int* srcs = lm;
    const int* dsts = lm + E;

    cudaFuncSetAttribute(gemm_mma_kernel,
                         cudaFuncAttributeMaxDynamicSharedMemorySize, SM_TOTAL);

    const int edge_blocks = (E + 31) / 32;    // 32 edges per block
    dim3 gemm_grid((M + 127) / 128, 2);

    wt_kernel<<<256, 128>>>(W1);
    gemm_mma_kernel<<<gemm_grid, 256, SM_TOTAL>>>(emb, b1, M);
    edge_kernel<<<edge_blocks, 256>>>(srcs, dsts, W2, b2, E, M);
    exp_kernel<<<EXP_BLOCKS, 256>>>(out, E);
    scale_kernel<<<SCALE_BLOCKS, 256>>>(out, E);
}

// round 11
// speedup vs baseline: 1.0875x; 1.0445x over previous
#include <cuda_runtime.h>
#include <cuda_fp16.h>
#include <math_constants.h>
#include <cstdint>

// Problem constants (registry shapes)
#define MAX_NODES 100000
#define HIDDEN 128
#define MAX_EDGES 1000000

#define EXP_BLOCKS 1024
#define SCALE_BLOCKS 1184

// Scratch (allocation-free rule: __device__ globals)
__device__ __half g_A[MAX_NODES * HIDDEN];      // emb @ W1[:128] + b1 (folded)
__device__ __half g_B[MAX_NODES * HIDDEN];      // emb @ W1[128:]
__device__ __half g_Wt[256 * 128];              // Wt[n][k] = Wcat[k][n], fp16
__device__ float g_logits[MAX_EDGES];
__device__ unsigned g_pmax2[256];               // bucketed max (orderable-uint keys)
__device__ float g_psum[EXP_BLOCKS];

__device__ __forceinline__ uint32_t smem_u32(const void* p) {
    uint32_t a;
    asm("{ .reg .u64 t; cvta.to.shared.u64 t, %1; cvt.u32.u64 %0, t; }"
        : "=r"(a) : "l"(p));
    return a;
}

// float <-> monotone-orderable uint (max is order-independent => atomics OK)
__device__ __forceinline__ unsigned fenc(float f) {
    unsigned u = __float_as_uint(f);
    return (u & 0x80000000u) ? ~u : (u | 0x80000000u);
}
__device__ __forceinline__ float fdec(unsigned u) {
    unsigned b = (u & 0x80000000u) ? (u & 0x7FFFFFFFu) : ~u;
    return __uint_as_float(b);
}

#define LDSM_X4(r0, r1, r2, r3, addr) asm volatile( \
    "ldmatrix.sync.aligned.m8n8.x4.shared.b16 {%0,%1,%2,%3}, [%4];" \
    : "=r"(r0), "=r"(r1), "=r"(r2), "=r"(r3) : "r"(addr))

#define MMA16816(c, a, b) asm volatile( \
    "mma.sync.aligned.m16n8k16.row.col.f32.f16.f16.f32 " \
    "{%0,%1,%2,%3}, {%4,%5,%6,%7}, {%8,%9}, {%0,%1,%2,%3};" \
    : "+f"((c)[0]), "+f"((c)[1]), "+f"((c)[2]), "+f"((c)[3]) \
    : "r"((a)[0]), "r"((a)[1]), "r"((a)[2]), "r"((a)[3]), \
      "r"((b)[0]), "r"((b)[1]))

// ---------------------------------------------------------------------------
// Prep: Wt[n][k] = W1[k][n] (n<128) | W1[128+k][n-128] (n>=128), as fp16.
// Also initializes the 256 max buckets.
// ---------------------------------------------------------------------------
__global__ void wt_kernel(const float* __restrict__ W1)
{
    int n = blockIdx.x;           // 0..255
    int k = threadIdx.x;          // 0..127
    if (k == 0) g_pmax2[n] = 0u;
    float v = (n < HIDDEN) ? W1[k * HIDDEN + n]
                           : W1[(HIDDEN + k) * HIDDEN + (n - HIDDEN)];
    g_Wt[n * HIDDEN + k] = __float2half_rn(v);
}

// ---------------------------------------------------------------------------
// Phase 1: HMMA GEMM (R8 form — fastest measured). N-split grid.y:
// 0 -> g_A half (+b1), 1 -> g_B half. Per CTA: D[128,128]. 256 threads,
// warp tile 32x64. Epilogue staged through SMEM for coalesced STG.128.
// ---------------------------------------------------------------------------
#define SMA_STRIDE 136
#define SB_OFF (128 * SMA_STRIDE * 2)                  // 34816
#define SM_TOTAL (SB_OFF + 128 * SMA_STRIDE * 2)       // 69632

__global__ __launch_bounds__(256, 2)
void gemm_mma_kernel(const float* __restrict__ emb, const float* __restrict__ b1, int M)
{
    extern __shared__ char smem[];
    __half* SA = (__half*)smem;
    __half* SB = (__half*)(smem + SB_OFF);
    const int tid = threadIdx.x;
    const int lane = tid & 31;
    const int wid = tid >> 5;
    const int m0 = blockIdx.x * 128;
    const int nb = blockIdx.y;

    // Load A tile: 128 rows x 128 k, fp32 -> fp16. 4096 float4, 16/thread.
#pragma unroll
    for (int i = 0; i < 16; i++) {
        int idx = tid + i * 256;
        int row = idx >> 5;
        int k4  = (idx & 31) * 4;
        float4 v = make_float4(0.f, 0.f, 0.f, 0.f);
        if (m0 + row < M) v = *(const float4*)(emb + (size_t)(m0 + row) * HIDDEN + k4);
        __half2 h01 = __floats2half2_rn(v.x, v.y);
        __half2 h23 = __floats2half2_rn(v.z, v.w);
        uint2 pack = make_uint2(*(uint32_t*)&h01, *(uint32_t*)&h23);
        *(uint2*)(SA + row * SMA_STRIDE + k4) = pack;
    }
    // Load B half-tile: 128 n x 128 k fp16 from g_Wt.
    const __half* WtB = g_Wt + (size_t)nb * 128 * HIDDEN;
#pragma unroll
    for (int i = 0; i < 16; i++) {
        int idx = tid + i * 256;
        int n   = idx >> 5;
        int k4  = (idx & 31) * 4;
        uint2 v = *(const uint2*)(WtB + n * HIDDEN + k4);
        *(uint2*)(SB + n * SMA_STRIDE + k4) = v;
    }
    __syncthreads();

    const int m_base = (wid >> 1) * 32;
    const int n_base = (wid & 1) * 64;
    const uint32_t sa = smem_u32(SA);
    const uint32_t sb = smem_u32(SB);

    float c[2][8][4];
#pragma unroll
    for (int mi = 0; mi < 2; mi++)
#pragma unroll
        for (int nj = 0; nj < 8; nj++)
#pragma unroll
            for (int q = 0; q < 4; q++) c[mi][nj][q] = 0.0f;

    const int arow = (lane & 7) + ((lane >> 3) & 1) * 8;
    const int akh  = ((lane >> 4) & 1) * 8;
    const int brow = lane & 7;
    const int bsel = lane >> 3;
    const int bnj  = (bsel >> 1) * 8;
    const int bkh  = (bsel & 1) * 8;

#pragma unroll
    for (int ks = 0; ks < 8; ks++) {
        const int k0 = ks * 16;
        uint32_t a[2][4];
#pragma unroll
        for (int mi = 0; mi < 2; mi++) {
            uint32_t addr = sa + (uint32_t)(((m_base + mi * 16 + arow) * SMA_STRIDE
                                             + k0 + akh) * 2);
            LDSM_X4(a[mi][0], a[mi][1], a[mi][2], a[mi][3], addr);
        }
        uint32_t b[8][2];
#pragma unroll
        for (int p = 0; p < 4; p++) {
            uint32_t addr = sb + (uint32_t)(((n_base + p * 16 + bnj + brow) * SMA_STRIDE
                                             + k0 + bkh) * 2);
            uint32_t r0, r1, r2, r3;
            LDSM_X4(r0, r1, r2, r3, addr);
            b[p * 2][0] = r0; b[p * 2][1] = r1;
            b[p * 2 + 1][0] = r2; b[p * 2 + 1][1] = r3;
        }
#pragma unroll
        for (int mi = 0; mi < 2; mi++)
#pragma unroll
            for (int nj = 0; nj < 8; nj++)
                MMA16816(c[mi][nj], a[mi], b[nj]);
    }

    // Epilogue stage 1: frags -> SA (stride 136 keeps STS conflict-free).
    __syncthreads();
    const int ncol = (lane & 3) * 2;
    const int mrow = lane >> 2;
#pragma unroll
    for (int mi = 0; mi < 2; mi++) {
        const int r0 = m_base + mi * 16 + mrow;
#pragma unroll
        for (int nj = 0; nj < 8; nj++) {
            int n = n_base + nj * 8 + ncol;
            float v0 = c[mi][nj][0], v1 = c[mi][nj][1];
            float v2 = c[mi][nj][2], v3 = c[mi][nj][3];
            if (nb == 0) {
                float bb0 = __ldg(b1 + n), bb1 = __ldg(b1 + n + 1);
                v0 += bb0; v1 += bb1; v2 += bb0; v3 += bb1;
            }
            *(__half2*)(SA + r0 * SMA_STRIDE + n)       = __floats2half2_rn(v0, v1);
            *(__half2*)(SA + (r0 + 8) * SMA_STRIDE + n) = __floats2half2_rn(v2, v3);
        }
    }
    __syncthreads();

    // Epilogue stage 2: coalesced STG.128. 2048 uint4, 8/thread.
    __half* dst_tbl = (nb == 0) ? g_A : g_B;
#pragma unroll
    for (int i = 0; i < 8; i++) {
        int idx = tid + i * 256;          // 0..2047
        int row = idx >> 4;               // 0..127
        int q   = (idx & 15) * 8;         // half offset within row
        if (m0 + row < M) {
            uint4 v = *(uint4*)(SA + row * SMA_STRIDE + q);
            *(uint4*)(dst_tbl + (size_t)(m0 + row) * HIDDEN + q) = v;
        }
    }
}

// ---------------------------------------------------------------------------
// Phase 2: per-edge logit. 8 lanes per edge, 4 edges per warp.
// CONTIGUOUS lane mapping: lane sub covers features [sub*8, sub*8+8) (load 1,
// byte offset sub*16 -> each 8-lane group = exactly one 128B line) and
// [64+sub*8, 64+sub*8+8) (load 2 -> the second line). Every line touched
// once and fully consumed: 4 L1tex wavefronts/edge (was 8 with the strided map).
// ---------------------------------------------------------------------------
__global__ __launch_bounds__(256) void edge_kernel(
    const int* __restrict__ srcs, const int* __restrict__ dsts,
    const float* __restrict__ W2, const float* __restrict__ b2,
    int E, int M)
{
    const int lane = threadIdx.x & 31;
    const int warp = threadIdx.x >> 5;    // 0..7
    const int grp  = lane >> 3;           // 0..3 edge within warp
    const int sub  = lane & 7;            // 0..7 feature slice
    const int e = (blockIdx.x * 8 + warp) * 4 + grp;

    // weights for features [sub*8, +8) and [64+sub*8, +8)
    float wlo[8], whi[8];
    {
        const float4* p0 = (const float4*)(W2 + sub * 8);
        const float4* p1 = (const float4*)(W2 + 64 + sub * 8);
        float4 v0 = p0[0], v1 = p0[1], v2 = p1[0], v3 = p1[1];
        wlo[0] = v0.x; wlo[1] = v0.y; wlo[2] = v0.z; wlo[3] = v0.w;
        wlo[4] = v1.x; wlo[5] = v1.y; wlo[6] = v1.z; wlo[7] = v1.w;
        whi[0] = v2.x; whi[1] = v2.y; whi[2] = v2.z; whi[3] = v2.w;
        whi[4] = v3.x; whi[5] = v3.y; whi[6] = v3.z; whi[7] = v3.w;
    }
    const float b2v = __ldg(b2);

    const bool has = (e < E);
    float p = 0.0f;
    if (has) {
        int s = srcs[e];
        int t = dsts[e];
        if ((unsigned)s >= (unsigned)M) s = 0;
        if ((unsigned)t >= (unsigned)M) t = 0;
        const __half* Ar = g_A + (size_t)s * HIDDEN;
        const __half* Br = g_B + (size_t)t * HIDDEN;
        uint4 a0  = *(const uint4*)(Ar + sub * 8);        // line 0 of A row
        uint4 a1  = *(const uint4*)(Ar + 64 + sub * 8);   // line 1 of A row
        uint4 b0  = *(const uint4*)(Br + sub * 8);        // line 0 of B row
        uint4 b1r = *(const uint4*)(Br + 64 + sub * 8);   // line 1 of B row

        const uint32_t* au  = (const uint32_t*)&a0;
        const uint32_t* bu  = (const uint32_t*)&b0;
#pragma unroll
        for (int i = 0; i < 4; i++) {
            float2 af = __half22float2(*(__half2*)&au[i]);
            float2 bf = __half22float2(*(__half2*)&bu[i]);
            float h0 = fmaxf(af.x + bf.x, 0.0f);
            float h1 = fmaxf(af.y + bf.y, 0.0f);
            p = fmaf(h0, wlo[2 * i], p);
            p = fmaf(h1, wlo[2 * i + 1], p);
        }
        const uint32_t* au2 = (const uint32_t*)&a1;
        const uint32_t* bu2 = (const uint32_t*)&b1r;
#pragma unroll
        for (int i = 0; i < 4; i++) {
            float2 af = __half22float2(*(__half2*)&au2[i]);
            float2 bf = __half22float2(*(__half2*)&bu2[i]);
            float h0 = fmaxf(af.x + bf.x, 0.0f);
            float h1 = fmaxf(af.y + bf.y, 0.0f);
            p = fmaf(h0, whi[2 * i], p);
            p = fmaf(h1, whi[2 * i + 1], p);
        }
    }
    p += __shfl_xor_sync(0xffffffffu, p, 4);
    p += __shfl_xor_sync(0xffffffffu, p, 2);
    p += __shfl_xor_sync(0xffffffffu, p, 1);
    const float logit = p + b2v;
    if (has && sub == 0) g_logits[e] = logit;

    float m = has ? logit : -CUDART_INF_F;
    m = fmaxf(m, __shfl_xor_sync(0xffffffffu, m, 8));
    m = fmaxf(m, __shfl_xor_sync(0xffffffffu, m, 16));
    if (lane == 0) atomicMax(&g_pmax2[blockIdx.x & 255], fenc(m));
}

// ---------------------------------------------------------------------------
// Phase 3: softmax. exp folds the 256-bucket max; scale folds the psum.
// ---------------------------------------------------------------------------
__global__ __launch_bounds__(256) void exp_kernel(float* __restrict__ out, int E)
{
    __shared__ float s[256];
    s[threadIdx.x] = fdec(g_pmax2[threadIdx.x]);
    __syncthreads();
#pragma unroll
    for (int o = 128; o > 0; o >>= 1) {
        if (threadIdx.x < o) s[threadIdx.x] = fmaxf(s[threadIdx.x], s[threadIdx.x + o]);
        __syncthreads();
    }
    const float m = s[0];
    __syncthreads();

    float acc = 0.0f;
    for (int i4 = (blockIdx.x * 256 + threadIdx.x) * 4; i4 < E; i4 += EXP_BLOCKS * 1024) {
        if (i4 + 3 < E) {
            float4 lg = *(const float4*)(g_logits + i4);
            float p0 = expf(lg.x - m), p1 = expf(lg.y - m);
            float p2 = expf(lg.z - m), p3 = expf(lg.w - m);
            *(float4*)(out + i4) = make_float4(p0, p1, p2, p3);
            acc += (p0 + p1) + (p2 + p3);
        } else {
            for (int i = i4; i < E; i++) {
                float p = expf(g_logits[i] - m);
                out[i] = p;
                acc += p;
            }
        }
    }
    s[threadIdx.x] = acc;
    __syncthreads();
#pragma unroll
    for (int o = 128; o > 0; o >>= 1) {
        if (threadIdx.x < o) s[threadIdx.x] += s[threadIdx.x + o];
        __syncthreads();
    }
    if (threadIdx.x == 0) g_psum[blockIdx.x] = s[0];
}

__global__ __launch_bounds__(256) void scale_kernel(float* __restrict__ out, int E)
{
    __shared__ float s[256];
    float a = 0.0f;
#pragma unroll
    for (int i = 0; i < EXP_BLOCKS / 256; i++)
        a += g_psum[threadIdx.x + i * 256];
    s[threadIdx.x] = a;
    __syncthreads();
#pragma unroll
    for (int o = 128; o > 0; o >>= 1) {
        if (threadIdx.x < o) s[threadIdx.x] += s[threadIdx.x + o];
        __syncthreads();
    }
    const float inv = 1.0f / s[0];

    const int stride = SCALE_BLOCKS * 1024;
    for (int i4 = (blockIdx.x * 256 + threadIdx.x) * 4; i4 < E; i4 += stride) {
        if (i4 + 3 < E) {
            float4 v = *(const float4*)(out + i4);
            v.x *= inv; v.y *= inv; v.z *= inv; v.w *= inv;
            *(float4*)(out + i4) = v;
        } else {
            for (int i = i4; i < E; i++) out[i] *= inv;
        }
    }
}

// ---------------------------------------------------------------------------
extern "C" void kernel_launch(void* const* d_in, const int* in_sizes, int n_in,
                              void* d_out, int out_size)
{
    const float* emb = (const float*)d_in[0];
    const int*   lm  = (const int*)d_in[1];   // int32 (JAX x64-disabled)
    const float* W1  = (const float*)d_in[2];
    const float* b1  = (const float*)d_in[3];
    const float* W2  = (const float*)d_in[4];
    const float* b2  = (const float*)d_in[5];
    float* out = (float*)d_out;

    const int M = in_sizes[0] / HIDDEN;       // number of nodes
    const int E = in_sizes[1] / 2;            // number of edges
    const int* srcs = lm;
    const int* dsts = lm + E;

    cudaFuncSetAttribute(gemm_mma_kernel,
                         cudaFuncAttributeMaxDynamicSharedMemorySize, SM_TOTAL);

    const int edge_blocks = (E + 31) / 32;    // 32 edges per block
    dim3 gemm_grid((M + 127) / 128, 2);

    wt_kernel<<<256, 128>>>(W1);
    gemm_mma_kernel<<<gemm_grid, 256, SM_TOTAL>>>(emb, b1, M);
    edge_kernel<<<edge_blocks, 256>>>(srcs, dsts, W2, b2, E, M);
    exp_kernel<<<EXP_BLOCKS, 256>>>(out, E);
    scale_kernel<<<SCALE_BLOCKS, 256>>>(out, E);
}

// round 12
// speedup vs baseline: 1.5181x; 1.3960x over previous
#include <cuda_runtime.h>
#include <cuda_fp16.h>
#include <math_constants.h>
#include <cstdint>

// Problem constants (registry shapes)
#define MAX_NODES 100000
#define HIDDEN 128
#define MAX_EDGES 1000000

#define EXP_BLOCKS 1024
#define SCALE_BLOCKS 1184

// Scratch (allocation-free rule: __device__ globals)
__device__ __half g_A[MAX_NODES * HIDDEN];      // emb @ W1[:128] + b1 (folded)
__device__ __half g_B[MAX_NODES * HIDDEN];      // emb @ W1[128:]
__device__ __half g_Wt[256 * 128];              // Wt[n][k] = Wcat[k][n], fp16
__device__ float g_logits[MAX_EDGES];
__device__ unsigned g_pmax2[256];               // bucketed max (orderable-uint keys)
__device__ float g_psum[EXP_BLOCKS];

__device__ __forceinline__ uint32_t smem_u32(const void* p) {
    uint32_t a;
    asm("{ .reg .u64 t; cvta.to.shared.u64 t, %1; cvt.u32.u64 %0, t; }"
        : "=r"(a) : "l"(p));
    return a;
}

// float <-> monotone-orderable uint (max is order-independent => atomics OK)
__device__ __forceinline__ unsigned fenc(float f) {
    unsigned u = __float_as_uint(f);
    return (u & 0x80000000u) ? ~u : (u | 0x80000000u);
}
__device__ __forceinline__ float fdec(unsigned u) {
    unsigned b = (u & 0x80000000u) ? (u & 0x7FFFFFFFu) : ~u;
    return __uint_as_float(b);
}

#define LDSM_X4(r0, r1, r2, r3, addr) asm volatile( \
    "ldmatrix.sync.aligned.m8n8.x4.shared.b16 {%0,%1,%2,%3}, [%4];" \
    : "=r"(r0), "=r"(r1), "=r"(r2), "=r"(r3) : "r"(addr))

#define MMA16816(c, a, b) asm volatile( \
    "mma.sync.aligned.m16n8k16.row.col.f32.f16.f16.f32 " \
    "{%0,%1,%2,%3}, {%4,%5,%6,%7}, {%8,%9}, {%0,%1,%2,%3};" \
    : "+f"((c)[0]), "+f"((c)[1]), "+f"((c)[2]), "+f"((c)[3]) \
    : "r"((a)[0]), "r"((a)[1]), "r"((a)[2]), "r"((a)[3]), \
      "r"((b)[0]), "r"((b)[1]))

// ---------------------------------------------------------------------------
// Prep: Wt[n][k] = W1[k][n] (n<128) | W1[128+k][n-128] (n>=128), as fp16.
// Also initializes the 256 max buckets.
// ---------------------------------------------------------------------------
__global__ void wt_kernel(const float* __restrict__ W1)
{
    int n = blockIdx.x;           // 0..255
    int k = threadIdx.x;          // 0..127
    if (k == 0) g_pmax2[n] = 0u;
    float v = (n < HIDDEN) ? W1[k * HIDDEN + n]
                           : W1[(HIDDEN + k) * HIDDEN + (n - HIDDEN)];
    g_Wt[n * HIDDEN + k] = __float2half_rn(v);
}

// ---------------------------------------------------------------------------
// Phase 1: HMMA GEMM (R8 form — fastest measured). N-split grid.y:
// 0 -> g_A half (+b1), 1 -> g_B half. Per CTA: D[128,128]. 256 threads,
// warp tile 32x64. Epilogue staged through SMEM for coalesced STG.128.
// ---------------------------------------------------------------------------
#define SMA_STRIDE 136
#define SB_OFF (128 * SMA_STRIDE * 2)                  // 34816
#define SM_TOTAL (SB_OFF + 128 * SMA_STRIDE * 2)       // 69632

__global__ __launch_bounds__(256, 2)
void gemm_mma_kernel(const float* __restrict__ emb, const float* __restrict__ b1, int M)
{
    extern __shared__ char smem[];
    __half* SA = (__half*)smem;
    __half* SB = (__half*)(smem + SB_OFF);
    const int tid = threadIdx.x;
    const int lane = tid & 31;
    const int wid = tid >> 5;
    const int m0 = blockIdx.x * 128;
    const int nb = blockIdx.y;

    // Load A tile: 128 rows x 128 k, fp32 -> fp16. 4096 float4, 16/thread.
#pragma unroll
    for (int i = 0; i < 16; i++) {
        int idx = tid + i * 256;
        int row = idx >> 5;
        int k4  = (idx & 31) * 4;
        float4 v = make_float4(0.f, 0.f, 0.f, 0.f);
        if (m0 + row < M) v = *(const float4*)(emb + (size_t)(m0 + row) * HIDDEN + k4);
        __half2 h01 = __floats2half2_rn(v.x, v.y);
        __half2 h23 = __floats2half2_rn(v.z, v.w);
        uint2 pack = make_uint2(*(uint32_t*)&h01, *(uint32_t*)&h23);
        *(uint2*)(SA + row * SMA_STRIDE + k4) = pack;
    }
    // Load B half-tile: 128 n x 128 k fp16 from g_Wt.
    const __half* WtB = g_Wt + (size_t)nb * 128 * HIDDEN;
#pragma unroll
    for (int i = 0; i < 16; i++) {
        int idx = tid + i * 256;
        int n   = idx >> 5;
        int k4  = (idx & 31) * 4;
        uint2 v = *(const uint2*)(WtB + n * HIDDEN + k4);
        *(uint2*)(SB + n * SMA_STRIDE + k4) = v;
    }
    __syncthreads();

    const int m_base = (wid >> 1) * 32;
    const int n_base = (wid & 1) * 64;
    const uint32_t sa = smem_u32(SA);
    const uint32_t sb = smem_u32(SB);

    float c[2][8][4];
#pragma unroll
    for (int mi = 0; mi < 2; mi++)
#pragma unroll
        for (int nj = 0; nj < 8; nj++)
#pragma unroll
            for (int q = 0; q < 4; q++) c[mi][nj][q] = 0.0f;

    const int arow = (lane & 7) + ((lane >> 3) & 1) * 8;
    const int akh  = ((lane >> 4) & 1) * 8;
    const int brow = lane & 7;
    const int bsel = lane >> 3;
    const int bnj  = (bsel >> 1) * 8;
    const int bkh  = (bsel & 1) * 8;

#pragma unroll
    for (int ks = 0; ks < 8; ks++) {
        const int k0 = ks * 16;
        uint32_t a[2][4];
#pragma unroll
        for (int mi = 0; mi < 2; mi++) {
            uint32_t addr = sa + (uint32_t)(((m_base + mi * 16 + arow) * SMA_STRIDE
                                             + k0 + akh) * 2);
            LDSM_X4(a[mi][0], a[mi][1], a[mi][2], a[mi][3], addr);
        }
        uint32_t b[8][2];
#pragma unroll
        for (int p = 0; p < 4; p++) {
            uint32_t addr = sb + (uint32_t)(((n_base + p * 16 + bnj + brow) * SMA_STRIDE
                                             + k0 + bkh) * 2);
            uint32_t r0, r1, r2, r3;
            LDSM_X4(r0, r1, r2, r3, addr);
            b[p * 2][0] = r0; b[p * 2][1] = r1;
            b[p * 2 + 1][0] = r2; b[p * 2 + 1][1] = r3;
        }
#pragma unroll
        for (int mi = 0; mi < 2; mi++)
#pragma unroll
            for (int nj = 0; nj < 8; nj++)
                MMA16816(c[mi][nj], a[mi], b[nj]);
    }

    // Epilogue stage 1: frags -> SA (stride 136 keeps STS conflict-free).
    __syncthreads();
    const int ncol = (lane & 3) * 2;
    const int mrow = lane >> 2;
#pragma unroll
    for (int mi = 0; mi < 2; mi++) {
        const int r0 = m_base + mi * 16 + mrow;
#pragma unroll
        for (int nj = 0; nj < 8; nj++) {
            int n = n_base + nj * 8 + ncol;
            float v0 = c[mi][nj][0], v1 = c[mi][nj][1];
            float v2 = c[mi][nj][2], v3 = c[mi][nj][3];
            if (nb == 0) {
                float bb0 = __ldg(b1 + n), bb1 = __ldg(b1 + n + 1);
                v0 += bb0; v1 += bb1; v2 += bb0; v3 += bb1;
            }
            *(__half2*)(SA + r0 * SMA_STRIDE + n)       = __floats2half2_rn(v0, v1);
            *(__half2*)(SA + (r0 + 8) * SMA_STRIDE + n) = __floats2half2_rn(v2, v3);
        }
    }
    __syncthreads();

    // Epilogue stage 2: coalesced STG.128. 2048 uint4, 8/thread.
    __half* dst_tbl = (nb == 0) ? g_A : g_B;
#pragma unroll
    for (int i = 0; i < 8; i++) {
        int idx = tid + i * 256;          // 0..2047
        int row = idx >> 4;               // 0..127
        int q   = (idx & 15) * 8;         // half offset within row
        if (m0 + row < M) {
            uint4 v = *(uint4*)(SA + row * SMA_STRIDE + q);
            *(uint4*)(dst_tbl + (size_t)(m0 + row) * HIDDEN + q) = v;
        }
    }
}

// ---------------------------------------------------------------------------
// Phase 2: per-edge logit. 8 lanes per edge-group; each group processes TWO
// edges (e, e+4) with all 8 gathers issued before any consumption (MLP=8/warp
// -> probes whether the phase is latency-bound vs LTS-random-bound).
// Contiguous lane map: lane sub covers features [sub*8,+8) and [64+sub*8,+8).
// ---------------------------------------------------------------------------
__device__ __forceinline__ float edge_dot(
    const uint4& a0, const uint4& a1, const uint4& b0, const uint4& b1r,
    const float* wlo, const float* whi)
{
    float p = 0.0f;
    const uint32_t* au  = (const uint32_t*)&a0;
    const uint32_t* bu  = (const uint32_t*)&b0;
#pragma unroll
    for (int i = 0; i < 4; i++) {
        float2 af = __half22float2(*(__half2*)&au[i]);
        float2 bf = __half22float2(*(__half2*)&bu[i]);
        float h0 = fmaxf(af.x + bf.x, 0.0f);
        float h1 = fmaxf(af.y + bf.y, 0.0f);
        p = fmaf(h0, wlo[2 * i], p);
        p = fmaf(h1, wlo[2 * i + 1], p);
    }
    const uint32_t* au2 = (const uint32_t*)&a1;
    const uint32_t* bu2 = (const uint32_t*)&b1r;
#pragma unroll
    for (int i = 0; i < 4; i++) {
        float2 af = __half22float2(*(__half2*)&au2[i]);
        float2 bf = __half22float2(*(__half2*)&bu2[i]);
        float h0 = fmaxf(af.x + bf.x, 0.0f);
        float h1 = fmaxf(af.y + bf.y, 0.0f);
        p = fmaf(h0, whi[2 * i], p);
        p = fmaf(h1, whi[2 * i + 1], p);
    }
    return p;
}

__global__ __launch_bounds__(256) void edge_kernel(
    const int* __restrict__ srcs, const int* __restrict__ dsts,
    const float* __restrict__ W2, const float* __restrict__ b2,
    int E, int M)
{
    const int lane = threadIdx.x & 31;
    const int warp = threadIdx.x >> 5;    // 0..7
    const int grp  = lane >> 3;           // 0..3
    const int sub  = lane & 7;            // 0..7 feature slice
    const int base = (blockIdx.x * 8 + warp) * 8;
    const int e0 = base + grp;
    const int e1 = base + grp + 4;

    float wlo[8], whi[8];
    {
        const float4* p0 = (const float4*)(W2 + sub * 8);
        const float4* p1 = (const float4*)(W2 + 64 + sub * 8);
        float4 v0 = p0[0], v1 = p0[1], v2 = p1[0], v3 = p1[1];
        wlo[0] = v0.x; wlo[1] = v0.y; wlo[2] = v0.z; wlo[3] = v0.w;
        wlo[4] = v1.x; wlo[5] = v1.y; wlo[6] = v1.z; wlo[7] = v1.w;
        whi[0] = v2.x; whi[1] = v2.y; whi[2] = v2.z; whi[3] = v2.w;
        whi[4] = v3.x; whi[5] = v3.y; whi[6] = v3.z; whi[7] = v3.w;
    }
    const float b2v = __ldg(b2);

    const bool h0 = (e0 < E);
    const bool h1 = (e1 < E);

    int s0 = 0, t0 = 0, s1 = 0, t1 = 0;
    if (h0) { s0 = srcs[e0]; t0 = dsts[e0]; }
    if (h1) { s1 = srcs[e1]; t1 = dsts[e1]; }
    if ((unsigned)s0 >= (unsigned)M) s0 = 0;
    if ((unsigned)t0 >= (unsigned)M) t0 = 0;
    if ((unsigned)s1 >= (unsigned)M) s1 = 0;
    if ((unsigned)t1 >= (unsigned)M) t1 = 0;

    // Issue all 8 gathers up front (independent LDG.128s).
    const __half* A0 = g_A + (size_t)s0 * HIDDEN;
    const __half* B0 = g_B + (size_t)t0 * HIDDEN;
    const __half* A1 = g_A + (size_t)s1 * HIDDEN;
    const __half* B1 = g_B + (size_t)t1 * HIDDEN;
    uint4 a00 = *(const uint4*)(A0 + sub * 8);
    uint4 a01 = *(const uint4*)(A0 + 64 + sub * 8);
    uint4 b00 = *(const uint4*)(B0 + sub * 8);
    uint4 b01 = *(const uint4*)(B0 + 64 + sub * 8);
    uint4 a10 = *(const uint4*)(A1 + sub * 8);
    uint4 a11 = *(const uint4*)(A1 + 64 + sub * 8);
    uint4 b10 = *(const uint4*)(B1 + sub * 8);
    uint4 b11 = *(const uint4*)(B1 + 64 + sub * 8);

    float p0 = edge_dot(a00, a01, b00, b01, wlo, whi);
    float p1 = edge_dot(a10, a11, b10, b11, wlo, whi);

    p0 += __shfl_xor_sync(0xffffffffu, p0, 4);
    p0 += __shfl_xor_sync(0xffffffffu, p0, 2);
    p0 += __shfl_xor_sync(0xffffffffu, p0, 1);
    p1 += __shfl_xor_sync(0xffffffffu, p1, 4);
    p1 += __shfl_xor_sync(0xffffffffu, p1, 2);
    p1 += __shfl_xor_sync(0xffffffffu, p1, 1);
    const float l0 = p0 + b2v;
    const float l1 = p1 + b2v;
    if (h0 && sub == 0) g_logits[e0] = l0;
    if (h1 && sub == 0) g_logits[e1] = l1;

    float m = fmaxf(h0 ? l0 : -CUDART_INF_F, h1 ? l1 : -CUDART_INF_F);
    m = fmaxf(m, __shfl_xor_sync(0xffffffffu, m, 8));
    m = fmaxf(m, __shfl_xor_sync(0xffffffffu, m, 16));
    if (lane == 0) atomicMax(&g_pmax2[blockIdx.x & 255], fenc(m));
}

// ---------------------------------------------------------------------------
// Phase 3: softmax. exp folds the 256-bucket max; scale folds the psum.
// ---------------------------------------------------------------------------
__global__ __launch_bounds__(256) void exp_kernel(float* __restrict__ out, int E)
{
    __shared__ float s[256];
    s[threadIdx.x] = fdec(g_pmax2[threadIdx.x]);
    __syncthreads();
#pragma unroll
    for (int o = 128; o > 0; o >>= 1) {
        if (threadIdx.x < o) s[threadIdx.x] = fmaxf(s[threadIdx.x], s[threadIdx.x + o]);
        __syncthreads();
    }
    const float m = s[0];
    __syncthreads();

    float acc = 0.0f;
    for (int i4 = (blockIdx.x * 256 + threadIdx.x) * 4; i4 < E; i4 += EXP_BLOCKS * 1024) {
        if (i4 + 3 < E) {
            float4 lg = *(const float4*)(g_logits + i4);
            float p0 = expf(lg.x - m), p1 = expf(lg.y - m);
            float p2 = expf(lg.z - m), p3 = expf(lg.w - m);
            *(float4*)(out + i4) = make_float4(p0, p1, p2, p3);
            acc += (p0 + p1) + (p2 + p3);
        } else {
            for (int i = i4; i < E; i++) {
                float p = expf(g_logits[i] - m);
                out[i] = p;
                acc += p;
            }
        }
    }
    s[threadIdx.x] = acc;
    __syncthreads();
#pragma unroll
    for (int o = 128; o > 0; o >>= 1) {
        if (threadIdx.x < o) s[threadIdx.x] += s[threadIdx.x + o];
        __syncthreads();
    }
    if (threadIdx.x == 0) g_psum[blockIdx.x] = s[0];
}

__global__ __launch_bounds__(256) void scale_kernel(float* __restrict__ out, int E)
{
    __shared__ float s[256];
    float a = 0.0f;
#pragma unroll
    for (int i = 0; i < EXP_BLOCKS / 256; i++)
        a += g_psum[threadIdx.x + i * 256];
    s[threadIdx.x] = a;
    __syncthreads();
#pragma unroll
    for (int o = 128; o > 0; o >>= 1) {
        if (threadIdx.x < o) s[threadIdx.x] += s[threadIdx.x + o];
        __syncthreads();
    }
    const float inv = 1.0f / s[0];

    const int stride = SCALE_BLOCKS * 1024;
    for (int i4 = (blockIdx.x * 256 + threadIdx.x) * 4; i4 < E; i4 += stride) {
        if (i4 + 3 < E) {
            float4 v = *(const float4*)(out + i4);
            v.x *= inv; v.y *= inv; v.z *= inv; v.w *= inv;
            *(float4*)(out + i4) = v;
        } else {
            for (int i = i4; i < E; i++) out[i] *= inv;
        }
    }
}

// ---------------------------------------------------------------------------
extern "C" void kernel_launch(void* const* d_in, const int* in_sizes, int n_in,
                              void* d_out, int out_size)
{
    const float* emb = (const float*)d_in[0];
    const int*   lm  = (const int*)d_in[1];   // int32 (JAX x64-disabled)
    const float* W1  = (const float*)d_in[2];
    const float* b1  = (const float*)d_in[3];
    const float* W2  = (const float*)d_in[4];
    const float* b2  = (const float*)d_in[5];
    float* out = (float*)d_out;

    const int M = in_sizes[0] / HIDDEN;       // number of nodes
    const int E = in_sizes[1] / 2;            // number of edges
    const int* srcs = lm;
    const int* dsts = lm + E;

    cudaFuncSetAttribute(gemm_mma_kernel,
                         cudaFuncAttributeMaxDynamicSharedMemorySize, SM_TOTAL);

    const int edge_blocks = (E + 63) / 64;    // 64 edges per block
    dim3 gemm_grid((M + 127) / 128, 2);

    wt_kernel<<<256, 128>>>(W1);
    gemm_mma_kernel<<<gemm_grid, 256, SM_TOTAL>>>(emb, b1, M);
    edge_kernel<<<edge_blocks, 256>>>(srcs, dsts, W2, b2, E, M);
    exp_kernel<<<EXP_BLOCKS, 256>>>(out, E);
    scale_kernel<<<SCALE_BLOCKS, 256>>>(out, E);
}

// round 13
// speedup vs baseline: 1.5508x; 1.0215x over previous
#include <cuda_runtime.h>
#include <cuda_fp16.h>
#include <math_constants.h>
#include <cstdint>

// Problem constants (registry shapes)
#define MAX_NODES 100000
#define HIDDEN 128
#define MAX_EDGES 1000000

#define MAX_EDGE_BLOCKS ((MAX_EDGES + 63) / 64)
#define SCALE_BLOCKS 1184

// Scratch (allocation-free rule: __device__ globals)
__device__ __half g_A[MAX_NODES * HIDDEN];      // emb @ W1[:128] + b1 (folded)
__device__ __half g_B[MAX_NODES * HIDDEN];      // emb @ W1[128:]
__device__ __half g_Wt[256 * 128];              // Wt[n][k] = Wcat[k][n], fp16
__device__ float g_psum[MAX_EDGE_BLOCKS];       // per-edge-block partial sums
__device__ float g_inv;

__device__ __forceinline__ uint32_t smem_u32(const void* p) {
    uint32_t a;
    asm("{ .reg .u64 t; cvta.to.shared.u64 t, %1; cvt.u32.u64 %0, t; }"
        : "=r"(a) : "l"(p));
    return a;
}

#define LDSM_X4(r0, r1, r2, r3, addr) asm volatile( \
    "ldmatrix.sync.aligned.m8n8.x4.shared.b16 {%0,%1,%2,%3}, [%4];" \
    : "=r"(r0), "=r"(r1), "=r"(r2), "=r"(r3) : "r"(addr))

#define MMA16816(c, a, b) asm volatile( \
    "mma.sync.aligned.m16n8k16.row.col.f32.f16.f16.f32 " \
    "{%0,%1,%2,%3}, {%4,%5,%6,%7}, {%8,%9}, {%0,%1,%2,%3};" \
    : "+f"((c)[0]), "+f"((c)[1]), "+f"((c)[2]), "+f"((c)[3]) \
    : "r"((a)[0]), "r"((a)[1]), "r"((a)[2]), "r"((a)[3]), \
      "r"((b)[0]), "r"((b)[1]))

// ---------------------------------------------------------------------------
// Prep: Wt[n][k] = W1[k][n] (n<128) | W1[128+k][n-128] (n>=128), as fp16.
// ---------------------------------------------------------------------------
__global__ void wt_kernel(const float* __restrict__ W1)
{
    int n = blockIdx.x;           // 0..255
    int k = threadIdx.x;          // 0..127
    float v = (n < HIDDEN) ? W1[k * HIDDEN + n]
                           : W1[(HIDDEN + k) * HIDDEN + (n - HIDDEN)];
    g_Wt[n * HIDDEN + k] = __float2half_rn(v);
}

// ---------------------------------------------------------------------------
// Phase 1: HMMA GEMM. grid = (2, mtiles): nb-adjacent CTAs share an emb
// tile and run concurrently, so the second read is L2-hot (halves DRAM).
// Per CTA: D[128,128]. 256 threads, warp tile 32x64; SMEM-staged epilogue.
// ---------------------------------------------------------------------------
#define SMA_STRIDE 136
#define SB_OFF (128 * SMA_STRIDE * 2)                  // 34816
#define SM_TOTAL (SB_OFF + 128 * SMA_STRIDE * 2)       // 69632

__global__ __launch_bounds__(256, 2)
void gemm_mma_kernel(const float* __restrict__ emb, const float* __restrict__ b1, int M)
{
    extern __shared__ char smem[];
    __half* SA = (__half*)smem;
    __half* SB = (__half*)(smem + SB_OFF);
    const int tid = threadIdx.x;
    const int lane = tid & 31;
    const int wid = tid >> 5;
    const int nb = blockIdx.x;                 // 0 -> g_A (+b1), 1 -> g_B
    const int m0 = blockIdx.y * 128;

    // Load A tile: 128 rows x 128 k, fp32 -> fp16. 4096 float4, 16/thread.
#pragma unroll
    for (int i = 0; i < 16; i++) {
        int idx = tid + i * 256;
        int row = idx >> 5;
        int k4  = (idx & 31) * 4;
        float4 v = make_float4(0.f, 0.f, 0.f, 0.f);
        if (m0 + row < M) v = *(const float4*)(emb + (size_t)(m0 + row) * HIDDEN + k4);
        __half2 h01 = __floats2half2_rn(v.x, v.y);
        __half2 h23 = __floats2half2_rn(v.z, v.w);
        uint2 pack = make_uint2(*(uint32_t*)&h01, *(uint32_t*)&h23);
        *(uint2*)(SA + row * SMA_STRIDE + k4) = pack;
    }
    // Load B half-tile: 128 n x 128 k fp16 from g_Wt.
    const __half* WtB = g_Wt + (size_t)nb * 128 * HIDDEN;
#pragma unroll
    for (int i = 0; i < 16; i++) {
        int idx = tid + i * 256;
        int n   = idx >> 5;
        int k4  = (idx & 31) * 4;
        uint2 v = *(const uint2*)(WtB + n * HIDDEN + k4);
        *(uint2*)(SB + n * SMA_STRIDE + k4) = v;
    }
    __syncthreads();

    const int m_base = (wid >> 1) * 32;
    const int n_base = (wid & 1) * 64;
    const uint32_t sa = smem_u32(SA);
    const uint32_t sb = smem_u32(SB);

    float c[2][8][4];
#pragma unroll
    for (int mi = 0; mi < 2; mi++)
#pragma unroll
        for (int nj = 0; nj < 8; nj++)
#pragma unroll
            for (int q = 0; q < 4; q++) c[mi][nj][q] = 0.0f;

    const int arow = (lane & 7) + ((lane >> 3) & 1) * 8;
    const int akh  = ((lane >> 4) & 1) * 8;
    const int brow = lane & 7;
    const int bsel = lane >> 3;
    const int bnj  = (bsel >> 1) * 8;
    const int bkh  = (bsel & 1) * 8;

#pragma unroll
    for (int ks = 0; ks < 8; ks++) {
        const int k0 = ks * 16;
        uint32_t a[2][4];
#pragma unroll
        for (int mi = 0; mi < 2; mi++) {
            uint32_t addr = sa + (uint32_t)(((m_base + mi * 16 + arow) * SMA_STRIDE
                                             + k0 + akh) * 2);
            LDSM_X4(a[mi][0], a[mi][1], a[mi][2], a[mi][3], addr);
        }
        uint32_t b[8][2];
#pragma unroll
        for (int p = 0; p < 4; p++) {
            uint32_t addr = sb + (uint32_t)(((n_base + p * 16 + bnj + brow) * SMA_STRIDE
                                             + k0 + bkh) * 2);
            uint32_t r0, r1, r2, r3;
            LDSM_X4(r0, r1, r2, r3, addr);
            b[p * 2][0] = r0; b[p * 2][1] = r1;
            b[p * 2 + 1][0] = r2; b[p * 2 + 1][1] = r3;
        }
#pragma unroll
        for (int mi = 0; mi < 2; mi++)
#pragma unroll
            for (int nj = 0; nj < 8; nj++)
                MMA16816(c[mi][nj], a[mi], b[nj]);
    }

    // Epilogue stage 1: frags -> SA (stride 136 keeps STS conflict-free).
    __syncthreads();
    const int ncol = (lane & 3) * 2;
    const int mrow = lane >> 2;
#pragma unroll
    for (int mi = 0; mi < 2; mi++) {
        const int r0 = m_base + mi * 16 + mrow;
#pragma unroll
        for (int nj = 0; nj < 8; nj++) {
            int n = n_base + nj * 8 + ncol;
            float v0 = c[mi][nj][0], v1 = c[mi][nj][1];
            float v2 = c[mi][nj][2], v3 = c[mi][nj][3];
            if (nb == 0) {
                float bb0 = __ldg(b1 + n), bb1 = __ldg(b1 + n + 1);
                v0 += bb0; v1 += bb1; v2 += bb0; v3 += bb1;
            }
            *(__half2*)(SA + r0 * SMA_STRIDE + n)       = __floats2half2_rn(v0, v1);
            *(__half2*)(SA + (r0 + 8) * SMA_STRIDE + n) = __floats2half2_rn(v2, v3);
        }
    }
    __syncthreads();

    // Epilogue stage 2: coalesced STG.128. 2048 uint4, 8/thread.
    __half* dst_tbl = (nb == 0) ? g_A : g_B;
#pragma unroll
    for (int i = 0; i < 8; i++) {
        int idx = tid + i * 256;          // 0..2047
        int row = idx >> 4;               // 0..127
        int q   = (idx & 15) * 8;         // half offset within row
        if (m0 + row < M) {
            uint4 v = *(uint4*)(SA + row * SMA_STRIDE + q);
            *(uint4*)(dst_tbl + (size_t)(m0 + row) * HIDDEN + q) = v;
        }
    }
}

// ---------------------------------------------------------------------------
// Phase 2: per-edge exp(logit). 8 lanes/edge-group, 2 edges/group (MLP=8/warp).
// No max subtraction (softmax is shift-invariant; logits are O(5), exp safe
// in fp32). Writes exp directly to out; deterministic fixed-order block sum
// into g_psum[blockIdx].
// ---------------------------------------------------------------------------
__device__ __forceinline__ float edge_dot(
    const uint4& a0, const uint4& a1, const uint4& b0, const uint4& b1r,
    const float* wlo, const float* whi)
{
    float p = 0.0f;
    const uint32_t* au  = (const uint32_t*)&a0;
    const uint32_t* bu  = (const uint32_t*)&b0;
#pragma unroll
    for (int i = 0; i < 4; i++) {
        float2 af = __half22float2(*(__half2*)&au[i]);
        float2 bf = __half22float2(*(__half2*)&bu[i]);
        float h0 = fmaxf(af.x + bf.x, 0.0f);
        float h1 = fmaxf(af.y + bf.y, 0.0f);
        p = fmaf(h0, wlo[2 * i], p);
        p = fmaf(h1, wlo[2 * i + 1], p);
    }
    const uint32_t* au2 = (const uint32_t*)&a1;
    const uint32_t* bu2 = (const uint32_t*)&b1r;
#pragma unroll
    for (int i = 0; i < 4; i++) {
        float2 af = __half22float2(*(__half2*)&au2[i]);
        float2 bf = __half22float2(*(__half2*)&bu2[i]);
        float h0 = fmaxf(af.x + bf.x, 0.0f);
        float h1 = fmaxf(af.y + bf.y, 0.0f);
        p = fmaf(h0, whi[2 * i], p);
        p = fmaf(h1, whi[2 * i + 1], p);
    }
    return p;
}

__global__ __launch_bounds__(256) void edge_kernel(
    const int* __restrict__ srcs, const int* __restrict__ dsts,
    const float* __restrict__ W2, const float* __restrict__ b2,
    float* __restrict__ out, int E, int M)
{
    const int lane = threadIdx.x & 31;
    const int warp = threadIdx.x >> 5;    // 0..7
    const int grp  = lane >> 3;           // 0..3
    const int sub  = lane & 7;            // 0..7 feature slice
    const int base = (blockIdx.x * 8 + warp) * 8;
    const int e0 = base + grp;
    const int e1 = base + grp + 4;

    float wlo[8], whi[8];
    {
        const float4* p0 = (const float4*)(W2 + sub * 8);
        const float4* p1 = (const float4*)(W2 + 64 + sub * 8);
        float4 v0 = p0[0], v1 = p0[1], v2 = p1[0], v3 = p1[1];
        wlo[0] = v0.x; wlo[1] = v0.y; wlo[2] = v0.z; wlo[3] = v0.w;
        wlo[4] = v1.x; wlo[5] = v1.y; wlo[6] = v1.z; wlo[7] = v1.w;
        whi[0] = v2.x; whi[1] = v2.y; whi[2] = v2.z; whi[3] = v2.w;
        whi[4] = v3.x; whi[5] = v3.y; whi[6] = v3.z; whi[7] = v3.w;
    }
    const float b2v = __ldg(b2);

    const bool h0 = (e0 < E);
    const bool h1 = (e1 < E);

    int s0 = 0, t0 = 0, s1 = 0, t1 = 0;
    if (h0) { s0 = srcs[e0]; t0 = dsts[e0]; }
    if (h1) { s1 = srcs[e1]; t1 = dsts[e1]; }
    if ((unsigned)s0 >= (unsigned)M) s0 = 0;
    if ((unsigned)t0 >= (unsigned)M) t0 = 0;
    if ((unsigned)s1 >= (unsigned)M) s1 = 0;
    if ((unsigned)t1 >= (unsigned)M) t1 = 0;

    // Issue all 8 gathers up front (independent LDG.128s).
    const __half* A0 = g_A + (size_t)s0 * HIDDEN;
    const __half* B0 = g_B + (size_t)t0 * HIDDEN;
    const __half* A1 = g_A + (size_t)s1 * HIDDEN;
    const __half* B1 = g_B + (size_t)t1 * HIDDEN;
    uint4 a00 = *(const uint4*)(A0 + sub * 8);
    uint4 a01 = *(const uint4*)(A0 + 64 + sub * 8);
    uint4 b00 = *(const uint4*)(B0 + sub * 8);
    uint4 b01 = *(const uint4*)(B0 + 64 + sub * 8);
    uint4 a10 = *(const uint4*)(A1 + sub * 8);
    uint4 a11 = *(const uint4*)(A1 + 64 + sub * 8);
    uint4 b10 = *(const uint4*)(B1 + sub * 8);
    uint4 b11 = *(const uint4*)(B1 + 64 + sub * 8);

    float p0 = edge_dot(a00, a01, b00, b01, wlo, whi);
    float p1 = edge_dot(a10, a11, b10, b11, wlo, whi);

    p0 += __shfl_xor_sync(0xffffffffu, p0, 4);
    p0 += __shfl_xor_sync(0xffffffffu, p0, 2);
    p0 += __shfl_xor_sync(0xffffffffu, p0, 1);
    p1 += __shfl_xor_sync(0xffffffffu, p1, 4);
    p1 += __shfl_xor_sync(0xffffffffu, p1, 2);
    p1 += __shfl_xor_sync(0xffffffffu, p1, 1);

    const float x0 = h0 ? expf(p0 + b2v) : 0.0f;
    const float x1 = h1 ? expf(p1 + b2v) : 0.0f;
    if (h0 && sub == 0) out[e0] = x0;
    if (h1 && sub == 0) out[e1] = x1;

    // Deterministic block sum: one contribution per group (sub==0 lanes:
    // 0, 8, 16, 24), fixed shfl order, then fixed-order tree over warps.
    float wsum = (sub == 0) ? (x0 + x1) : 0.0f;
    wsum += __shfl_xor_sync(0xffffffffu, wsum, 8);
    wsum += __shfl_xor_sync(0xffffffffu, wsum, 16);

    __shared__ float ssum[8];
    if (lane == 0) ssum[warp] = wsum;
    __syncthreads();
    if (threadIdx.x == 0) {
        float a = ((ssum[0] + ssum[1]) + (ssum[2] + ssum[3]))
                + ((ssum[4] + ssum[5]) + (ssum[6] + ssum[7]));
        g_psum[blockIdx.x] = a;
    }
}

// ---------------------------------------------------------------------------
// Phase 3: 1-block deterministic sum of per-block partials -> g_inv.
// ---------------------------------------------------------------------------
__global__ __launch_bounds__(1024) void reduce_sum_kernel(int nblocks)
{
    __shared__ float s[1024];
    float a = 0.0f;
    for (int i = threadIdx.x; i < nblocks; i += 1024) a += g_psum[i];
    s[threadIdx.x] = a;
    __syncthreads();
#pragma unroll
    for (int o = 512; o > 0; o >>= 1) {
        if (threadIdx.x < o) s[threadIdx.x] += s[threadIdx.x + o];
        __syncthreads();
    }
    if (threadIdx.x == 0) g_inv = 1.0f / s[0];
}

__global__ __launch_bounds__(256) void scale_kernel(float* __restrict__ out, int E)
{
    const float inv = g_inv;
    const int stride = SCALE_BLOCKS * 1024;
    for (int i4 = (blockIdx.x * 256 + threadIdx.x) * 4; i4 < E; i4 += stride) {
        if (i4 + 3 < E) {
            float4 v = *(const float4*)(out + i4);
            v.x *= inv; v.y *= inv; v.z *= inv; v.w *= inv;
            *(float4*)(out + i4) = v;
        } else {
            for (int i = i4; i < E; i++) out[i] *= inv;
        }
    }
}

// ---------------------------------------------------------------------------
extern "C" void kernel_launch(void* const* d_in, const int* in_sizes, int n_in,
                              void* d_out, int out_size)
{
    const float* emb = (const float*)d_in[0];
    const int*   lm  = (const int*)d_in[1];   // int32 (JAX x64-disabled)
    const float* W1  = (const float*)d_in[2];
    const float* b1  = (const float*)d_in[3];
    const float* W2  = (const float*)d_in[4];
    const float* b2  = (const float*)d_in[5];
    float* out = (float*)d_out;

    const int M = in_sizes[0] / HIDDEN;       // number of nodes
    const int E = in_sizes[1] / 2;            // number of edges
    const int* srcs = lm;
    const int* dsts = lm + E;

    cudaFuncSetAttribute(gemm_mma_kernel,
                         cudaFuncAttributeMaxDynamicSharedMemorySize, SM_TOTAL);

    const int edge_blocks = (E + 63) / 64;    // 64 edges per block
    dim3 gemm_grid(2, (M + 127) / 128);       // nb-adjacent: emb read L2-hot

    wt_kernel<<<256, 128>>>(W1);
    gemm_mma_kernel<<<gemm_grid, 256, SM_TOTAL>>>(emb, b1, M);
    edge_kernel<<<edge_blocks, 256>>>(srcs, dsts, W2, b2, out, E, M);
    reduce_sum_kernel<<<1, 1024>>>(edge_blocks);
    scale_kernel<<<SCALE_BLOCKS, 256>>>(out, E);
}

// round 15
// speedup vs baseline: 1.6193x; 1.0442x over previous
#include <cuda_runtime.h>
#include <cuda_fp16.h>
#include <math_constants.h>
#include <cstdint>

// Problem constants (registry shapes)
#define MAX_NODES 100000
#define HIDDEN 128
#define MAX_EDGES 1000000

#define EDGES_PER_BLOCK 96
#define MAX_EDGE_BLOCKS ((MAX_EDGES + EDGES_PER_BLOCK - 1) / EDGES_PER_BLOCK)
#define SCALE_BLOCKS 1184

// Scratch (allocation-free rule: __device__ globals)
__device__ __half g_A[MAX_NODES * HIDDEN];      // emb @ W1[:128] + b1 (folded)
__device__ __half g_B[MAX_NODES * HIDDEN];      // emb @ W1[128:]
__device__ __half g_Wt[256 * 128];              // Wt[n][k] = Wcat[k][n], fp16
__device__ float g_psum[MAX_EDGE_BLOCKS];       // per-edge-block partial sums

__device__ __forceinline__ uint32_t smem_u32(const void* p) {
    uint32_t a;
    asm("{ .reg .u64 t; cvta.to.shared.u64 t, %1; cvt.u32.u64 %0, t; }"
        : "=r"(a) : "l"(p));
    return a;
}

#define LDSM_X4(r0, r1, r2, r3, addr) asm volatile( \
    "ldmatrix.sync.aligned.m8n8.x4.shared.b16 {%0,%1,%2,%3}, [%4];" \
    : "=r"(r0), "=r"(r1), "=r"(r2), "=r"(r3) : "r"(addr))

#define MMA16816(c, a, b) asm volatile( \
    "mma.sync.aligned.m16n8k16.row.col.f32.f16.f16.f32 " \
    "{%0,%1,%2,%3}, {%4,%5,%6,%7}, {%8,%9}, {%0,%1,%2,%3};" \
    : "+f"((c)[0]), "+f"((c)[1]), "+f"((c)[2]), "+f"((c)[3]) \
    : "r"((a)[0]), "r"((a)[1]), "r"((a)[2]), "r"((a)[3]), \
      "r"((b)[0]), "r"((b)[1]))

// ---------------------------------------------------------------------------
// Prep: Wt[n][k] = W1[k][n] (n<128) | W1[128+k][n-128] (n>=128), as fp16.
// ---------------------------------------------------------------------------
__global__ void wt_kernel(const float* __restrict__ W1)
{
    int n = blockIdx.x;           // 0..255
    int k = threadIdx.x;          // 0..127
    float v = (n < HIDDEN) ? W1[k * HIDDEN + n]
                           : W1[(HIDDEN + k) * HIDDEN + (n - HIDDEN)];
    g_Wt[n * HIDDEN + k] = __float2half_rn(v);
}

// ---------------------------------------------------------------------------
// Phase 1: HMMA GEMM. grid = (2, mtiles). Per CTA: D[128,128]. 256 threads,
// warp tile 32x64; SMEM-staged epilogue for coalesced STG.128.
// ---------------------------------------------------------------------------
#define SMA_STRIDE 136
#define SB_OFF (128 * SMA_STRIDE * 2)                  // 34816
#define SM_TOTAL (SB_OFF + 128 * SMA_STRIDE * 2)       // 69632

__global__ __launch_bounds__(256, 2)
void gemm_mma_kernel(const float* __restrict__ emb, const float* __restrict__ b1, int M)
{
    extern __shared__ char smem[];
    __half* SA = (__half*)smem;
    __half* SB = (__half*)(smem + SB_OFF);
    const int tid = threadIdx.x;
    const int lane = tid & 31;
    const int wid = tid >> 5;
    const int nb = blockIdx.x;                 // 0 -> g_A (+b1), 1 -> g_B
    const int m0 = blockIdx.y * 128;

    // Load A tile: 128 rows x 128 k, fp32 -> fp16. 4096 float4, 16/thread.
#pragma unroll
    for (int i = 0; i < 16; i++) {
        int idx = tid + i * 256;
        int row = idx >> 5;
        int k4  = (idx & 31) * 4;
        float4 v = make_float4(0.f, 0.f, 0.f, 0.f);
        if (m0 + row < M) v = *(const float4*)(emb + (size_t)(m0 + row) * HIDDEN + k4);
        __half2 h01 = __floats2half2_rn(v.x, v.y);
        __half2 h23 = __floats2half2_rn(v.z, v.w);
        uint2 pack = make_uint2(*(uint32_t*)&h01, *(uint32_t*)&h23);
        *(uint2*)(SA + row * SMA_STRIDE + k4) = pack;
    }
    // Load B half-tile: 128 n x 128 k fp16 from g_Wt.
    const __half* WtB = g_Wt + (size_t)nb * 128 * HIDDEN;
#pragma unroll
    for (int i = 0; i < 16; i++) {
        int idx = tid + i * 256;
        int n   = idx >> 5;
        int k4  = (idx & 31) * 4;
        uint2 v = *(const uint2*)(WtB + n * HIDDEN + k4);
        *(uint2*)(SB + n * SMA_STRIDE + k4) = v;
    }
    __syncthreads();

    const int m_base = (wid >> 1) * 32;
    const int n_base = (wid & 1) * 64;
    const uint32_t sa = smem_u32(SA);
    const uint32_t sb = smem_u32(SB);

    float c[2][8][4];
#pragma unroll
    for (int mi = 0; mi < 2; mi++)
#pragma unroll
        for (int nj = 0; nj < 8; nj++)
#pragma unroll
            for (int q = 0; q < 4; q++) c[mi][nj][q] = 0.0f;

    const int arow = (lane & 7) + ((lane >> 3) & 1) * 8;
    const int akh  = ((lane >> 4) & 1) * 8;
    const int brow = lane & 7;
    const int bsel = lane >> 3;
    const int bnj  = (bsel >> 1) * 8;
    const int bkh  = (bsel & 1) * 8;

#pragma unroll
    for (int ks = 0; ks < 8; ks++) {
        const int k0 = ks * 16;
        uint32_t a[2][4];
#pragma unroll
        for (int mi = 0; mi < 2; mi++) {
            uint32_t addr = sa + (uint32_t)(((m_base + mi * 16 + arow) * SMA_STRIDE
                                             + k0 + akh) * 2);
            LDSM_X4(a[mi][0], a[mi][1], a[mi][2], a[mi][3], addr);
        }
        uint32_t b[8][2];
#pragma unroll
        for (int p = 0; p < 4; p++) {
            uint32_t addr = sb + (uint32_t)(((n_base + p * 16 + bnj + brow) * SMA_STRIDE
                                             + k0 + bkh) * 2);
            uint32_t r0, r1, r2, r3;
            LDSM_X4(r0, r1, r2, r3, addr);
            b[p * 2][0] = r0; b[p * 2][1] = r1;
            b[p * 2 + 1][0] = r2; b[p * 2 + 1][1] = r3;
        }
#pragma unroll
        for (int mi = 0; mi < 2; mi++)
#pragma unroll
            for (int nj = 0; nj < 8; nj++)
                MMA16816(c[mi][nj], a[mi], b[nj]);
    }

    // Epilogue stage 1: frags -> SA (stride 136 keeps STS conflict-free).
    __syncthreads();
    const int ncol = (lane & 3) * 2;
    const int mrow = lane >> 2;
#pragma unroll
    for (int mi = 0; mi < 2; mi++) {
        const int r0 = m_base + mi * 16 + mrow;
#pragma unroll
        for (int nj = 0; nj < 8; nj++) {
            int n = n_base + nj * 8 + ncol;
            float v0 = c[mi][nj][0], v1 = c[mi][nj][1];
            float v2 = c[mi][nj][2], v3 = c[mi][nj][3];
            if (nb == 0) {
                float bb0 = __ldg(b1 + n), bb1 = __ldg(b1 + n + 1);
                v0 += bb0; v1 += bb1; v2 += bb0; v3 += bb1;
            }
            *(__half2*)(SA + r0 * SMA_STRIDE + n)       = __floats2half2_rn(v0, v1);
            *(__half2*)(SA + (r0 + 8) * SMA_STRIDE + n) = __floats2half2_rn(v2, v3);
        }
    }
    __syncthreads();

    // Epilogue stage 2: coalesced STG.128. 2048 uint4, 8/thread.
    __half* dst_tbl = (nb == 0) ? g_A : g_B;
#pragma unroll
    for (int i = 0; i < 8; i++) {
        int idx = tid + i * 256;          // 0..2047
        int row = idx >> 4;               // 0..127
        int q   = (idx & 15) * 8;         // half offset within row
        if (m0 + row < M) {
            uint4 v = *(uint4*)(SA + row * SMA_STRIDE + q);
            *(uint4*)(dst_tbl + (size_t)(m0 + row) * HIDDEN + q) = v;
        }
    }
}

// ---------------------------------------------------------------------------
// Phase 2: per-edge exp(logit). 8 lanes/edge-group, THREE edges/group
// (12 gathers in flight per warp: latency-hiding, R12 showed this phase is
// latency-bound). No max subtraction (shift-invariant softmax; logits O(5)).
// Writes exp directly to out + deterministic fixed-order block partial sums.
// ---------------------------------------------------------------------------
__device__ __forceinline__ float edge_dot(
    const uint4& a0, const uint4& a1, const uint4& b0, const uint4& b1r,
    const float* wlo, const float* whi)
{
    float p = 0.0f;
    const uint32_t* au  = (const uint32_t*)&a0;
    const uint32_t* bu  = (const uint32_t*)&b0;
#pragma unroll
    for (int i = 0; i < 4; i++) {
        float2 af = __half22float2(*(__half2*)&au[i]);
        float2 bf = __half22float2(*(__half2*)&bu[i]);
        float h0 = fmaxf(af.x + bf.x, 0.0f);
        float h1 = fmaxf(af.y + bf.y, 0.0f);
        p = fmaf(h0, wlo[2 * i], p);
        p = fmaf(h1, wlo[2 * i + 1], p);
    }
    const uint32_t* au2 = (const uint32_t*)&a1;
    const uint32_t* bu2 = (const uint32_t*)&b1r;
#pragma unroll
    for (int i = 0; i < 4; i++) {
        float2 af = __half22float2(*(__half2*)&au2[i]);
        float2 bf = __half22float2(*(__half2*)&bu2[i]);
        float h0 = fmaxf(af.x + bf.x, 0.0f);
        float h1 = fmaxf(af.y + bf.y, 0.0f);
        p = fmaf(h0, whi[2 * i], p);
        p = fmaf(h1, whi[2 * i + 1], p);
    }
    return p;
}

__global__ __launch_bounds__(256) void edge_kernel(
    const int* __restrict__ srcs, const int* __restrict__ dsts,
    const float* __restrict__ W2, const float* __restrict__ b2,
    float* __restrict__ out, int E, int M)
{
    const int lane = threadIdx.x & 31;
    const int warp = threadIdx.x >> 5;    // 0..7
    const int grp  = lane >> 3;           // 0..3
    const int sub  = lane & 7;            // 0..7 feature slice
    const int base = (blockIdx.x * 8 + warp) * 12;

    float wlo[8], whi[8];
    {
        const float4* p0 = (const float4*)(W2 + sub * 8);
        const float4* p1 = (const float4*)(W2 + 64 + sub * 8);
        float4 v0 = p0[0], v1 = p0[1], v2 = p1[0], v3 = p1[1];
        wlo[0] = v0.x; wlo[1] = v0.y; wlo[2] = v0.z; wlo[3] = v0.w;
        wlo[4] = v1.x; wlo[5] = v1.y; wlo[6] = v1.z; wlo[7] = v1.w;
        whi[0] = v2.x; whi[1] = v2.y; whi[2] = v2.z; whi[3] = v2.w;
        whi[4] = v3.x; whi[5] = v3.y; whi[6] = v3.z; whi[7] = v3.w;
    }
    const float b2v = __ldg(b2);

    int e[3];
    bool h[3];
    int s[3], t[3];
#pragma unroll
    for (int j = 0; j < 3; j++) {
        e[j] = base + grp + j * 4;
        h[j] = (e[j] < E);
        s[j] = 0; t[j] = 0;
        if (h[j]) { s[j] = srcs[e[j]]; t[j] = dsts[e[j]]; }
        if ((unsigned)s[j] >= (unsigned)M) s[j] = 0;
        if ((unsigned)t[j] >= (unsigned)M) t[j] = 0;
    }

    // Issue all 12 gathers up front (independent LDG.128s).
    uint4 av0[3], av1[3], bv0[3], bv1[3];
#pragma unroll
    for (int j = 0; j < 3; j++) {
        const __half* Ar = g_A + (size_t)s[j] * HIDDEN;
        const __half* Br = g_B + (size_t)t[j] * HIDDEN;
        av0[j] = *(const uint4*)(Ar + sub * 8);
        av1[j] = *(const uint4*)(Ar + 64 + sub * 8);
        bv0[j] = *(const uint4*)(Br + sub * 8);
        bv1[j] = *(const uint4*)(Br + 64 + sub * 8);
    }

    float x[3];
#pragma unroll
    for (int j = 0; j < 3; j++) {
        float p = edge_dot(av0[j], av1[j], bv0[j], bv1[j], wlo, whi);
        p += __shfl_xor_sync(0xffffffffu, p, 4);
        p += __shfl_xor_sync(0xffffffffu, p, 2);
        p += __shfl_xor_sync(0xffffffffu, p, 1);
        x[j] = h[j] ? expf(p + b2v) : 0.0f;
        if (h[j] && sub == 0) out[e[j]] = x[j];
    }

    // Deterministic block sum: contributions from sub==0 lanes (0,8,16,24),
    // fixed shfl order, fixed-order tree over warps.
    float wsum = (sub == 0) ? ((x[0] + x[1]) + x[2]) : 0.0f;
    wsum += __shfl_xor_sync(0xffffffffu, wsum, 8);
    wsum += __shfl_xor_sync(0xffffffffu, wsum, 16);

    __shared__ float ssum[8];
    if (lane == 0) ssum[warp] = wsum;
    __syncthreads();
    if (threadIdx.x == 0) {
        float a = ((ssum[0] + ssum[1]) + (ssum[2] + ssum[3]))
                + ((ssum[4] + ssum[5]) + (ssum[6] + ssum[7]));
        g_psum[blockIdx.x] = a;
    }
}

// ---------------------------------------------------------------------------
// Phase 3: scale. Every block redundantly reduces the partial sums in an
// identical fixed order (deterministic, L2-hot array) -> no separate launch.
// ---------------------------------------------------------------------------
__global__ __launch_bounds__(256) void scale_kernel(
    float* __restrict__ out, int E, int nblocks)
{
    __shared__ float s[256];
    float a = 0.0f;
    for (int i = threadIdx.x; i < nblocks; i += 256) a += g_psum[i];
    s[threadIdx.x] = a;
    __syncthreads();
#pragma unroll
    for (int o = 128; o > 0; o >>= 1) {
        if (threadIdx.x < o) s[threadIdx.x] += s[threadIdx.x + o];
        __syncthreads();
    }
    const float inv = 1.0f / s[0];

    const int stride = SCALE_BLOCKS * 1024;
    for (int i4 = (blockIdx.x * 256 + threadIdx.x) * 4; i4 < E; i4 += stride) {
        if (i4 + 3 < E) {
            float4 v = *(const float4*)(out + i4);
            v.x *= inv; v.y *= inv; v.z *= inv; v.w *= inv;
            *(float4*)(out + i4) = v;
        } else {
            for (int i = i4; i < E; i++) out[i] *= inv;
        }
    }
}

// ---------------------------------------------------------------------------
extern "C" void kernel_launch(void* const* d_in, const int* in_sizes, int n_in,
                              void* d_out, int out_size)
{
    const float* emb = (const float*)d_in[0];
    const int*   lm  = (const int*)d_in[1];   // int32 (JAX x64-disabled)
    const float* W1  = (const float*)d_in[2];
    const float* b1  = (const float*)d_in[3];
    const float* W2  = (const float*)d_in[4];
    const float* b2  = (const float*)d_in[5];
    float* out = (float*)d_out;

    const int M = in_sizes[0] / HIDDEN;       // number of nodes
    const int E = in_sizes[1] / 2;            // number of edges
    const int* srcs = lm;
    const int* dsts = lm + E;

    cudaFuncSetAttribute(gemm_mma_kernel,
                         cudaFuncAttributeMaxDynamicSharedMemorySize, SM_TOTAL);

    const int edge_blocks = (E + EDGES_PER_BLOCK - 1) / EDGES_PER_BLOCK;
    dim3 gemm_grid(2, (M + 127) / 128);

    wt_kernel<<<256, 128>>>(W1);
    gemm_mma_kernel<<<gemm_grid, 256, SM_TOTAL>>>(emb, b1, M);
    edge_kernel<<<edge_blocks, 256>>>(srcs, dsts, W2, b2, out, E, M);
    scale_kernel<<<SCALE_BLOCKS, 256>>>(out, E, edge_blocks);
}